// round 1
// baseline (speedup 1.0000x reference)
#include <cuda_runtime.h>
#include <cuda_bf16.h>
#include <float.h>
#include <math.h>

// ---------------- problem constants ----------------
#define NL   12
#define D    768
#define NH   12
#define HD   64
#define VV   50257
#define BB   4
#define TT   1024
#define BT   (BB*TT)          // 4096
#define FF   (4*D)            // 3072
#define BH   (BB*NH)          // 48
#define EPSF 1e-5f
#define SCALE 0.125f          // HD^-0.5

// ---------------- scratch (device globals; no runtime alloc) ----------------
__device__ float g_x[BT*D];
__device__ float g_h[BT*D];
__device__ float g_q[BT*D];
__device__ float g_k[BT*D];
__device__ float g_v[BT*D];
__device__ float g_o[BT*D];
__device__ float g_ff[BT*FF];
__device__ float g_att[(size_t)BH*TT*TT];   // 201 MB
__device__ float g_nll[BT];

// ---------------- embedding ----------------
__global__ void embed_kernel(const int* __restrict__ idx,
                             const float* __restrict__ tok,
                             const float* __restrict__ pos,
                             float* __restrict__ x) {
    int i = blockIdx.x * 256 + threadIdx.x;
    if (i >= BT * D) return;
    int row = i / D;
    int d   = i - row * D;
    int t   = row & (TT - 1);
    x[i] = tok[(size_t)idx[row] * D + d] + pos[(size_t)t * D + d];
}

// ---------------- layernorm (one block per row) ----------------
__global__ void ln_kernel(const float* __restrict__ x,
                          const float* __restrict__ g,
                          const float* __restrict__ b,
                          float* __restrict__ out) {
    int row = blockIdx.x;
    const float* xr = x + (size_t)row * D;
    __shared__ float sx[D];
    __shared__ float red[256];
    int tid = threadIdx.x;

    float s = 0.f;
    for (int i = tid; i < D; i += 256) { float t = xr[i]; sx[i] = t; s += t; }
    red[tid] = s; __syncthreads();
    #pragma unroll
    for (int off = 128; off > 0; off >>= 1) {
        if (tid < off) red[tid] += red[tid + off];
        __syncthreads();
    }
    float mean = red[0] * (1.f / D);
    __syncthreads();

    float s2 = 0.f;
    for (int i = tid; i < D; i += 256) { float t = sx[i] - mean; s2 += t * t; }
    red[tid] = s2; __syncthreads();
    #pragma unroll
    for (int off = 128; off > 0; off >>= 1) {
        if (tid < off) red[tid] += red[tid + off];
        __syncthreads();
    }
    float rstd = rsqrtf(red[0] * (1.f / D) + EPSF);

    float* orow = out + (size_t)row * D;
    for (int i = tid; i < D; i += 256)
        orow[i] = (sx[i] - mean) * rstd * g[i] + b[i];
}

// ---------------- generic SGEMM: C = op(A[M,K] @ B[K,N] (+bias) (+resid)) ----------------
// 128x128 block tile, BK=16, 256 threads, 8x8 microtile.
__global__ void gemm_nn(const float* __restrict__ A, const float* __restrict__ Bm,
                        const float* __restrict__ bias, const float* __restrict__ resid,
                        float* __restrict__ C, int M, int N, int K, int relu) {
    __shared__ float As[16][132];   // [k][m], padded
    __shared__ float Bs[16][128];   // [k][n]
    int bn = blockIdx.x, bm = blockIdx.y;
    int tid = threadIdx.x;
    int tx = tid & 15, ty = tid >> 4;
    int m0 = ty * 8, n0 = tx * 8;
    int gm = bm * 128, gn = bn * 128;

    float acc[8][8];
    #pragma unroll
    for (int i = 0; i < 8; i++)
        #pragma unroll
        for (int j = 0; j < 8; j++) acc[i][j] = 0.f;

    const float* Ab = A + (size_t)gm * K;
    for (int k0 = 0; k0 < K; k0 += 16) {
        #pragma unroll
        for (int i = 0; i < 8; i++) {
            int idx = tid + i * 256;        // 0..2047
            int m = idx >> 4, kk = idx & 15;
            As[kk][m] = Ab[(size_t)m * K + k0 + kk];
        }
        #pragma unroll
        for (int i = 0; i < 8; i++) {
            int idx = tid + i * 256;
            int kk = idx >> 7, n = idx & 127;
            int col = gn + n;
            Bs[kk][n] = (col < N) ? Bm[(size_t)(k0 + kk) * N + col] : 0.f;
        }
        __syncthreads();
        #pragma unroll
        for (int kk = 0; kk < 16; kk++) {
            float a[8], b[8];
            #pragma unroll
            for (int i = 0; i < 8; i++) a[i] = As[kk][m0 + i];
            #pragma unroll
            for (int j = 0; j < 8; j++) b[j] = Bs[kk][n0 + j];
            #pragma unroll
            for (int i = 0; i < 8; i++)
                #pragma unroll
                for (int j = 0; j < 8; j++)
                    acc[i][j] = fmaf(a[i], b[j], acc[i][j]);
        }
        __syncthreads();
    }

    #pragma unroll
    for (int i = 0; i < 8; i++) {
        int rowg = gm + m0 + i;
        #pragma unroll
        for (int j = 0; j < 8; j++) {
            int colg = gn + n0 + j;
            if (colg < N) {
                float v = acc[i][j];
                if (bias)  v += bias[colg];
                if (resid) v += resid[(size_t)rowg * N + colg];
                if (relu)  v = fmaxf(v, 0.f);
                C[(size_t)rowg * N + colg] = v;
            }
        }
    }
}

// ---------------- attention: scores = scale * Q K^T with causal mask ----------------
// grid (tblk=16, sblk=16, bh=48); each block: 64x64 tile, K=64.
__global__ void attn_scores(const float* __restrict__ q, const float* __restrict__ k,
                            float* __restrict__ att) {
    int tb = blockIdx.x, sb = blockIdx.y, bh = blockIdx.z;
    if (sb > tb) return;
    int b = bh / NH, h = bh % NH;

    __shared__ float Qs[64][65];   // [d][m]
    __shared__ float Ks[64][65];   // [d][n]
    int tid = threadIdx.x;

    const float* qb = q + (size_t)b * TT * D + (size_t)h * HD;
    const float* kb = k + (size_t)b * TT * D + (size_t)h * HD;
    #pragma unroll
    for (int i = 0; i < 16; i++) {
        int idx = tid + i * 256;            // 0..4095
        int m = idx >> 6, d = idx & 63;
        Qs[d][m] = qb[(size_t)(tb * 64 + m) * D + d];
        Ks[d][m] = kb[(size_t)(sb * 64 + m) * D + d];
    }
    __syncthreads();

    int tx = tid & 15, ty = tid >> 4;
    int m0 = ty * 4, n0 = tx * 4;
    float acc[4][4];
    #pragma unroll
    for (int i = 0; i < 4; i++)
        #pragma unroll
        for (int j = 0; j < 4; j++) acc[i][j] = 0.f;

    #pragma unroll
    for (int d = 0; d < 64; d++) {
        float a[4], bv[4];
        #pragma unroll
        for (int i = 0; i < 4; i++) a[i]  = Qs[d][m0 + i];
        #pragma unroll
        for (int j = 0; j < 4; j++) bv[j] = Ks[d][n0 + j];
        #pragma unroll
        for (int i = 0; i < 4; i++)
            #pragma unroll
            for (int j = 0; j < 4; j++)
                acc[i][j] = fmaf(a[i], bv[j], acc[i][j]);
    }

    float* out = att + ((size_t)bh * TT + (size_t)tb * 64) * TT + (size_t)sb * 64;
    #pragma unroll
    for (int i = 0; i < 4; i++) {
        int t = tb * 64 + m0 + i;
        #pragma unroll
        for (int j = 0; j < 4; j++) {
            int s = sb * 64 + n0 + j;
            out[(size_t)(m0 + i) * TT + n0 + j] =
                (s <= t) ? acc[i][j] * SCALE : -3.402823466e38f;
        }
    }
}

// ---------------- attention row softmax (causal; one block per (bh,t) row) ----------------
__global__ void attn_softmax(float* __restrict__ att) {
    int row = blockIdx.x;                   // bh*TT + t
    int t = row & (TT - 1);
    float* p = att + (size_t)row * TT;
    int L = ((t >> 6) + 1) << 6;            // ceil to 64 (covers masked diag part)
    int tid = threadIdx.x;

    float m = -FLT_MAX, s = 0.f;
    for (int i = tid; i < L; i += 256) {
        float x = p[i];
        if (x > m) { s = s * expf(m - x) + 1.f; m = x; }
        else        s += expf(x - m);
    }
    __shared__ float sm[256], ss[256];
    sm[tid] = m; ss[tid] = s; __syncthreads();
    #pragma unroll
    for (int off = 128; off > 0; off >>= 1) {
        if (tid < off) {
            float m2 = sm[tid + off], s2 = ss[tid + off];
            float M = fmaxf(sm[tid], m2);
            ss[tid] = ss[tid] * expf(sm[tid] - M) + s2 * expf(m2 - M);
            sm[tid] = M;
        }
        __syncthreads();
    }
    float gm = sm[0];
    float inv = 1.f / ss[0];
    for (int i = tid; i < L; i += 256)
        p[i] = expf(p[i] - gm) * inv;       // masked entries -> exp(-inf)=0
}

// ---------------- attention PV: O = P @ V  (grid: (tblk=16, bh=48)) ----------------
__global__ void attn_pv(const float* __restrict__ att, const float* __restrict__ v,
                        float* __restrict__ o) {
    int tb = blockIdx.x, bh = blockIdx.y;
    int b = bh / NH, h = bh % NH;

    __shared__ float Ps[32][68];            // [k][m] padded
    __shared__ float Vs[32][64];            // [k][n]
    int tid = threadIdx.x;
    int tx = tid & 15, ty = tid >> 4;
    int m0 = ty * 4, n0 = tx * 4;

    float acc[4][4];
    #pragma unroll
    for (int i = 0; i < 4; i++)
        #pragma unroll
        for (int j = 0; j < 4; j++) acc[i][j] = 0.f;

    const float* arow = att + ((size_t)bh * TT + (size_t)tb * 64) * TT;
    const float* vb = v + (size_t)b * TT * D + (size_t)h * HD;
    int Smax = (tb + 1) * 64;

    for (int s0 = 0; s0 < Smax; s0 += 32) {
        #pragma unroll
        for (int i = 0; i < 8; i++) {
            int idx = tid + i * 256;        // 64x32 = 2048
            int m = idx >> 5, kk = idx & 31;
            Ps[kk][m] = arow[(size_t)m * TT + s0 + kk];
        }
        #pragma unroll
        for (int i = 0; i < 8; i++) {
            int idx = tid + i * 256;        // 32x64 = 2048
            int kk = idx >> 6, n = idx & 63;
            Vs[kk][n] = vb[(size_t)(s0 + kk) * D + n];
        }
        __syncthreads();
        #pragma unroll
        for (int kk = 0; kk < 32; kk++) {
            float a[4], bv[4];
            #pragma unroll
            for (int i = 0; i < 4; i++) a[i]  = Ps[kk][m0 + i];
            #pragma unroll
            for (int j = 0; j < 4; j++) bv[j] = Vs[kk][n0 + j];
            #pragma unroll
            for (int i = 0; i < 4; i++)
                #pragma unroll
                for (int j = 0; j < 4; j++)
                    acc[i][j] = fmaf(a[i], bv[j], acc[i][j]);
        }
        __syncthreads();
    }

    float* ob = o + (size_t)(b * TT + tb * 64) * D + (size_t)h * HD;
    #pragma unroll
    for (int i = 0; i < 4; i++)
        #pragma unroll
        for (int j = 0; j < 4; j++)
            ob[(size_t)(m0 + i) * D + n0 + j] = acc[i][j];
}

// ---------------- per-row NLL over vocab ----------------
__global__ void nll_kernel(const float* __restrict__ logits,
                           const int* __restrict__ targets,
                           float* __restrict__ nll) {
    int row = blockIdx.x;
    const float* lr = logits + (size_t)row * VV;
    int tid = threadIdx.x;

    float m = -FLT_MAX, s = 0.f;
    for (int i = tid; i < VV; i += 256) {
        float x = lr[i];
        if (x > m) { s = s * expf(m - x) + 1.f; m = x; }
        else        s += expf(x - m);
    }
    __shared__ float sm[256], ss[256];
    sm[tid] = m; ss[tid] = s; __syncthreads();
    #pragma unroll
    for (int off = 128; off > 0; off >>= 1) {
        if (tid < off) {
            float m2 = sm[tid + off], s2 = ss[tid + off];
            float M = fmaxf(sm[tid], m2);
            ss[tid] = ss[tid] * expf(sm[tid] - M) + s2 * expf(m2 - M);
            sm[tid] = M;
        }
        __syncthreads();
    }
    if (tid == 0)
        nll[row] = sm[0] + logf(ss[0]) - lr[targets[row]];
}

__global__ void loss_kernel(const float* __restrict__ nll, float* __restrict__ dst,
                            int nextra) {
    __shared__ float red[256];
    int tid = threadIdx.x;
    float s = 0.f;
    for (int i = tid; i < BT; i += 256) s += nll[i];
    red[tid] = s; __syncthreads();
    #pragma unroll
    for (int off = 128; off > 0; off >>= 1) {
        if (tid < off) red[tid] += red[tid + off];
        __syncthreads();
    }
    if (tid == 0) {
        float loss = red[0] * (1.f / BT);
        for (int i = 0; i < nextra; i++) dst[i] = loss;
    }
}

// ---------------- launch ----------------
extern "C" void kernel_launch(void* const* d_in, const int* in_sizes, int n_in,
                              void* d_out, int out_size) {
    const int*   idx     = (const int*)  d_in[0];
    const int*   targets = (const int*)  d_in[1];
    const float* tok_emb = (const float*)d_in[2];
    const float* pos_emb = (const float*)d_in[3];
    const float* Wq      = (const float*)d_in[4];
    const float* Wk      = (const float*)d_in[5];
    const float* Wv      = (const float*)d_in[6];
    const float* Wo      = (const float*)d_in[7];
    const float* bo      = (const float*)d_in[8];
    const float* ln1_g   = (const float*)d_in[9];
    const float* ln1_b   = (const float*)d_in[10];
    const float* ln2_g   = (const float*)d_in[11];
    const float* ln2_b   = (const float*)d_in[12];
    const float* W1      = (const float*)d_in[13];
    const float* b1      = (const float*)d_in[14];
    const float* W2      = (const float*)d_in[15];
    const float* b2      = (const float*)d_in[16];
    const float* Wlm     = (const float*)d_in[17];
    const float* blm     = (const float*)d_in[18];

    float *x, *h, *q, *k, *v, *o, *ff, *att, *nll;
    cudaGetSymbolAddress((void**)&x,   g_x);
    cudaGetSymbolAddress((void**)&h,   g_h);
    cudaGetSymbolAddress((void**)&q,   g_q);
    cudaGetSymbolAddress((void**)&k,   g_k);
    cudaGetSymbolAddress((void**)&v,   g_v);
    cudaGetSymbolAddress((void**)&o,   g_o);
    cudaGetSymbolAddress((void**)&ff,  g_ff);
    cudaGetSymbolAddress((void**)&att, g_att);
    cudaGetSymbolAddress((void**)&nll, g_nll);

    embed_kernel<<<(BT * D + 255) / 256, 256>>>(idx, tok_emb, pos_emb, x);

    dim3 gD((D + 127) / 128, BT / 128);       // 6 x 32
    dim3 gF((FF + 127) / 128, BT / 128);      // 24 x 32
    dim3 gV((VV + 127) / 128, BT / 128);      // 393 x 32

    for (int l = 0; l < NL; l++) {
        const float* wq = Wq + (size_t)l * D * D;
        const float* wk = Wk + (size_t)l * D * D;
        const float* wv = Wv + (size_t)l * D * D;
        const float* wo = Wo + (size_t)l * D * D;
        const float* w1 = W1 + (size_t)l * D * FF;
        const float* w2 = W2 + (size_t)l * FF * D;

        ln_kernel<<<BT, 256>>>(x, ln1_g + (size_t)l * D, ln1_b + (size_t)l * D, h);
        gemm_nn<<<gD, 256>>>(h, wq, nullptr, nullptr, q, BT, D, D, 0);
        gemm_nn<<<gD, 256>>>(h, wk, nullptr, nullptr, k, BT, D, D, 0);
        gemm_nn<<<gD, 256>>>(h, wv, nullptr, nullptr, v, BT, D, D, 0);

        attn_scores<<<dim3(TT / 64, TT / 64, BH), 256>>>(q, k, att);
        attn_softmax<<<BH * TT, 256>>>(att);
        attn_pv<<<dim3(TT / 64, BH), 256>>>(att, v, o);

        gemm_nn<<<gD, 256>>>(o, wo, bo + (size_t)l * D, x, x, BT, D, D, 0);

        ln_kernel<<<BT, 256>>>(x, ln2_g + (size_t)l * D, ln2_b + (size_t)l * D, h);
        gemm_nn<<<gF, 256>>>(h, w1, b1 + (size_t)l * FF, nullptr, ff, BT, FF, D, 1);
        gemm_nn<<<gD, 256>>>(ff, w2, b2 + (size_t)l * D, x, x, BT, D, FF, 0);
    }

    float* logits = (float*)d_out;
    gemm_nn<<<gV, 256>>>(x, Wlm, blm, nullptr, logits, BT, VV, D, 0);

    long long btv = (long long)BT * VV;
    if ((long long)out_size > btv) {
        nll_kernel<<<BT, 256>>>(logits, targets, nll);
        loss_kernel<<<1, 256>>>(nll, logits + btv, (int)((long long)out_size - btv));
    }
}

// round 2
// speedup vs baseline: 1.6004x; 1.6004x over previous
#include <cuda_runtime.h>
#include <cuda_bf16.h>
#include <float.h>
#include <math.h>

// ---------------- problem constants ----------------
#define NL   12
#define D    768
#define NH   12
#define HD   64
#define VV   50257
#define BB   4
#define TT   1024
#define BT   (BB*TT)          // 4096
#define FF   (4*D)            // 3072
#define BH   (BB*NH)          // 48
#define EPSF 1e-5f
#define SCALE 0.125f          // HD^-0.5

// ---------------- scratch (device globals; no runtime alloc) ----------------
__device__ float g_x[BT*D];
__device__ float g_h[BT*D];
__device__ float g_q[BT*D];
__device__ float g_k[BT*D];
__device__ float g_v[BT*D];
__device__ float g_o[BT*D];
__device__ float g_ff[BT*FF];
__device__ float g_att[(size_t)BH*TT*TT];   // 201 MB
__device__ float g_nll[BT];

// ---------------- tf32 helpers ----------------
__device__ __forceinline__ unsigned f2tf(float x) {
    unsigned r;
    asm("cvt.rna.tf32.f32 %0, %1;" : "=r"(r) : "f"(x));
    return r;
}
__device__ __forceinline__ void mma_tf32(float* d, const unsigned* a, const unsigned* b) {
    asm volatile(
        "mma.sync.aligned.m16n8k8.row.col.f32.tf32.tf32.f32 "
        "{%0,%1,%2,%3}, {%4,%5,%6,%7}, {%8,%9}, {%0,%1,%2,%3};"
        : "+f"(d[0]), "+f"(d[1]), "+f"(d[2]), "+f"(d[3])
        : "r"(a[0]), "r"(a[1]), "r"(a[2]), "r"(a[3]), "r"(b[0]), "r"(b[1]));
}

// ---------------- embedding ----------------
__global__ void embed_kernel(const int* __restrict__ idx,
                             const float* __restrict__ tok,
                             const float* __restrict__ pos,
                             float* __restrict__ x) {
    int i = blockIdx.x * 256 + threadIdx.x;
    if (i >= BT * D) return;
    int row = i / D;
    int d   = i - row * D;
    int t   = row & (TT - 1);
    x[i] = tok[(size_t)idx[row] * D + d] + pos[(size_t)t * D + d];
}

// ---------------- layernorm (one block per row) ----------------
__global__ void ln_kernel(const float* __restrict__ x,
                          const float* __restrict__ g,
                          const float* __restrict__ b,
                          float* __restrict__ out) {
    int row = blockIdx.x;
    const float* xr = x + (size_t)row * D;
    __shared__ float sx[D];
    __shared__ float red[256];
    int tid = threadIdx.x;

    float s = 0.f;
    for (int i = tid; i < D; i += 256) { float t = xr[i]; sx[i] = t; s += t; }
    red[tid] = s; __syncthreads();
    #pragma unroll
    for (int off = 128; off > 0; off >>= 1) {
        if (tid < off) red[tid] += red[tid + off];
        __syncthreads();
    }
    float mean = red[0] * (1.f / D);
    __syncthreads();

    float s2 = 0.f;
    for (int i = tid; i < D; i += 256) { float t = sx[i] - mean; s2 += t * t; }
    red[tid] = s2; __syncthreads();
    #pragma unroll
    for (int off = 128; off > 0; off >>= 1) {
        if (tid < off) red[tid] += red[tid + off];
        __syncthreads();
    }
    float rstd = rsqrtf(red[0] * (1.f / D) + EPSF);

    float* orow = out + (size_t)row * D;
    for (int i = tid; i < D; i += 256)
        orow[i] = (sx[i] - mean) * rstd * g[i] + b[i];
}

// ---------------- TF32 tensor-core GEMM ----------------
// C[M,N] = A[M,K] @ B[K,N] (+bias) (+resid) (relu?)
// 128x128x32 block tile, 256 threads, 8 warps as 4(M) x 2(N), warp tile 32x64.
// Grid: x = M/128 (M-major so LM-head weight columns stay L2-resident), y = ceil(N/128).
#define APAD 129
__global__ __launch_bounds__(256, 2)
void gemm_tf32(const float* __restrict__ A, const float* __restrict__ Bm,
               const float* __restrict__ bias, const float* __restrict__ resid,
               float* __restrict__ C, int M, int N, int K, int relu) {
    __shared__ unsigned As[32][APAD];   // [k][m]
    __shared__ unsigned Bs[32][APAD];   // [k][n]

    const int tid  = threadIdx.x;
    const int lane = tid & 31;
    const int wid  = tid >> 5;
    const int warpM = (wid >> 1) * 32;   // 0,32,64,96
    const int warpN = (wid & 1) * 64;    // 0,64
    const int gm = blockIdx.x * 128;
    const int gn = blockIdx.y * 128;
    const int lt = lane & 3;        // thread-in-group (k sub)
    const int lg = lane >> 2;       // group id (row/col sub)

    float acc[2][8][4];
    #pragma unroll
    for (int mi = 0; mi < 2; mi++)
        #pragma unroll
        for (int nj = 0; nj < 8; nj++)
            #pragma unroll
            for (int r = 0; r < 4; r++) acc[mi][nj][r] = 0.f;

    const bool vecB = ((N & 3) == 0) && (gn + 128 <= N);

    for (int k0 = 0; k0 < K; k0 += 32) {
        // ---- load A tile 128x32 (always full rows; M,K multiples) ----
        #pragma unroll
        for (int i = 0; i < 4; i++) {
            int f  = i * 256 + tid;        // 0..1023 float4 slots
            int am = f >> 3;               // 0..127
            int ak = (f & 7) << 2;         // 0,4,..,28
            const float4 v = *(const float4*)(A + (size_t)(gm + am) * K + k0 + ak);
            As[ak + 0][am] = f2tf(v.x);
            As[ak + 1][am] = f2tf(v.y);
            As[ak + 2][am] = f2tf(v.z);
            As[ak + 3][am] = f2tf(v.w);
        }
        // ---- load B tile 32x128 ----
        if (vecB) {
            #pragma unroll
            for (int i = 0; i < 4; i++) {
                int f  = i * 256 + tid;
                int bk = f >> 5;              // 0..31
                int bn = (f & 31) << 2;       // 0,4,..,124
                const float4 v = *(const float4*)(Bm + (size_t)(k0 + bk) * N + gn + bn);
                Bs[bk][bn + 0] = f2tf(v.x);
                Bs[bk][bn + 1] = f2tf(v.y);
                Bs[bk][bn + 2] = f2tf(v.z);
                Bs[bk][bn + 3] = f2tf(v.w);
            }
        } else {
            #pragma unroll
            for (int i = 0; i < 16; i++) {
                int f  = i * 256 + tid;       // 0..4095 scalars
                int bk = f >> 7;              // 0..31
                int bn = f & 127;
                int col = gn + bn;
                float v = (col < N) ? Bm[(size_t)(k0 + bk) * N + col] : 0.f;
                Bs[bk][bn] = f2tf(v);
            }
        }
        __syncthreads();

        // ---- 4 k-steps of 8 ----
        #pragma unroll
        for (int kk = 0; kk < 32; kk += 8) {
            unsigned a[2][4], b[8][2];
            #pragma unroll
            for (int mi = 0; mi < 2; mi++) {
                int mr = warpM + mi * 16 + lg;
                a[mi][0] = As[kk + lt    ][mr    ];
                a[mi][1] = As[kk + lt    ][mr + 8];
                a[mi][2] = As[kk + lt + 4][mr    ];
                a[mi][3] = As[kk + lt + 4][mr + 8];
            }
            #pragma unroll
            for (int nj = 0; nj < 8; nj++) {
                int nc = warpN + nj * 8 + lg;
                b[nj][0] = Bs[kk + lt    ][nc];
                b[nj][1] = Bs[kk + lt + 4][nc];
            }
            #pragma unroll
            for (int mi = 0; mi < 2; mi++)
                #pragma unroll
                for (int nj = 0; nj < 8; nj++)
                    mma_tf32(acc[mi][nj], a[mi], b[nj]);
        }
        __syncthreads();
    }

    // ---- epilogue ----
    #pragma unroll
    for (int mi = 0; mi < 2; mi++) {
        int r0 = gm + warpM + mi * 16 + lg;
        #pragma unroll
        for (int nj = 0; nj < 8; nj++) {
            int c0 = gn + warpN + nj * 8 + (lt << 1);
            #pragma unroll
            for (int r = 0; r < 4; r++) {
                int rowg = r0 + ((r >> 1) << 3);     // +8 for r=2,3
                int colg = c0 + (r & 1);
                if (colg < N) {
                    float v = acc[mi][nj][r];
                    if (bias)  v += bias[colg];
                    if (resid) v += resid[(size_t)rowg * N + colg];
                    if (relu)  v = fmaxf(v, 0.f);
                    C[(size_t)rowg * N + colg] = v;
                }
            }
        }
    }
}

// ---------------- attention: scores = scale * Q K^T with causal mask ----------------
__global__ void attn_scores(const float* __restrict__ q, const float* __restrict__ k,
                            float* __restrict__ att) {
    int tb = blockIdx.x, sb = blockIdx.y, bh = blockIdx.z;
    if (sb > tb) return;
    int b = bh / NH, h = bh % NH;

    __shared__ float Qs[64][65];
    __shared__ float Ks[64][65];
    int tid = threadIdx.x;

    const float* qb = q + (size_t)b * TT * D + (size_t)h * HD;
    const float* kb = k + (size_t)b * TT * D + (size_t)h * HD;
    #pragma unroll
    for (int i = 0; i < 16; i++) {
        int idx = tid + i * 256;
        int m = idx >> 6, d = idx & 63;
        Qs[d][m] = qb[(size_t)(tb * 64 + m) * D + d];
        Ks[d][m] = kb[(size_t)(sb * 64 + m) * D + d];
    }
    __syncthreads();

    int tx = tid & 15, ty = tid >> 4;
    int m0 = ty * 4, n0 = tx * 4;
    float acc[4][4];
    #pragma unroll
    for (int i = 0; i < 4; i++)
        #pragma unroll
        for (int j = 0; j < 4; j++) acc[i][j] = 0.f;

    #pragma unroll
    for (int d = 0; d < 64; d++) {
        float a[4], bv[4];
        #pragma unroll
        for (int i = 0; i < 4; i++) a[i]  = Qs[d][m0 + i];
        #pragma unroll
        for (int j = 0; j < 4; j++) bv[j] = Ks[d][n0 + j];
        #pragma unroll
        for (int i = 0; i < 4; i++)
            #pragma unroll
            for (int j = 0; j < 4; j++)
                acc[i][j] = fmaf(a[i], bv[j], acc[i][j]);
    }

    float* out = att + ((size_t)bh * TT + (size_t)tb * 64) * TT + (size_t)sb * 64;
    #pragma unroll
    for (int i = 0; i < 4; i++) {
        int t = tb * 64 + m0 + i;
        #pragma unroll
        for (int j = 0; j < 4; j++) {
            int s = sb * 64 + n0 + j;
            out[(size_t)(m0 + i) * TT + n0 + j] =
                (s <= t) ? acc[i][j] * SCALE : -3.402823466e38f;
        }
    }
}

// ---------------- attention row softmax ----------------
__global__ void attn_softmax(float* __restrict__ att) {
    int row = blockIdx.x;
    int t = row & (TT - 1);
    float* p = att + (size_t)row * TT;
    int L = ((t >> 6) + 1) << 6;
    int tid = threadIdx.x;

    float m = -FLT_MAX, s = 0.f;
    for (int i = tid; i < L; i += 256) {
        float x = p[i];
        if (x > m) { s = s * expf(m - x) + 1.f; m = x; }
        else        s += expf(x - m);
    }
    __shared__ float sm[256], ss[256];
    sm[tid] = m; ss[tid] = s; __syncthreads();
    #pragma unroll
    for (int off = 128; off > 0; off >>= 1) {
        if (tid < off) {
            float m2 = sm[tid + off], s2 = ss[tid + off];
            float M = fmaxf(sm[tid], m2);
            ss[tid] = ss[tid] * expf(sm[tid] - M) + s2 * expf(m2 - M);
            sm[tid] = M;
        }
        __syncthreads();
    }
    float gm = sm[0];
    float inv = 1.f / ss[0];
    for (int i = tid; i < L; i += 256)
        p[i] = expf(p[i] - gm) * inv;
}

// ---------------- attention PV ----------------
__global__ void attn_pv(const float* __restrict__ att, const float* __restrict__ v,
                        float* __restrict__ o) {
    int tb = blockIdx.x, bh = blockIdx.y;
    int b = bh / NH, h = bh % NH;

    __shared__ float Ps[32][68];
    __shared__ float Vs[32][64];
    int tid = threadIdx.x;
    int tx = tid & 15, ty = tid >> 4;
    int m0 = ty * 4, n0 = tx * 4;

    float acc[4][4];
    #pragma unroll
    for (int i = 0; i < 4; i++)
        #pragma unroll
        for (int j = 0; j < 4; j++) acc[i][j] = 0.f;

    const float* arow = att + ((size_t)bh * TT + (size_t)tb * 64) * TT;
    const float* vb = v + (size_t)b * TT * D + (size_t)h * HD;
    int Smax = (tb + 1) * 64;

    for (int s0 = 0; s0 < Smax; s0 += 32) {
        #pragma unroll
        for (int i = 0; i < 8; i++) {
            int idx = tid + i * 256;
            int m = idx >> 5, kk = idx & 31;
            Ps[kk][m] = arow[(size_t)m * TT + s0 + kk];
        }
        #pragma unroll
        for (int i = 0; i < 8; i++) {
            int idx = tid + i * 256;
            int kk = idx >> 6, n = idx & 63;
            Vs[kk][n] = vb[(size_t)(s0 + kk) * D + n];
        }
        __syncthreads();
        #pragma unroll
        for (int kk = 0; kk < 32; kk++) {
            float a[4], bv[4];
            #pragma unroll
            for (int i = 0; i < 4; i++) a[i]  = Ps[kk][m0 + i];
            #pragma unroll
            for (int j = 0; j < 4; j++) bv[j] = Vs[kk][n0 + j];
            #pragma unroll
            for (int i = 0; i < 4; i++)
                #pragma unroll
                for (int j = 0; j < 4; j++)
                    acc[i][j] = fmaf(a[i], bv[j], acc[i][j]);
        }
        __syncthreads();
    }

    float* ob = o + (size_t)(b * TT + tb * 64) * D + (size_t)h * HD;
    #pragma unroll
    for (int i = 0; i < 4; i++)
        #pragma unroll
        for (int j = 0; j < 4; j++)
            ob[(size_t)(m0 + i) * D + n0 + j] = acc[i][j];
}

// ---------------- per-row NLL over vocab ----------------
__global__ void nll_kernel(const float* __restrict__ logits,
                           const int* __restrict__ targets,
                           float* __restrict__ nll) {
    int row = blockIdx.x;
    const float* lr = logits + (size_t)row * VV;
    int tid = threadIdx.x;

    float m = -FLT_MAX, s = 0.f;
    for (int i = tid; i < VV; i += 256) {
        float x = lr[i];
        if (x > m) { s = s * expf(m - x) + 1.f; m = x; }
        else        s += expf(x - m);
    }
    __shared__ float sm[256], ss[256];
    sm[tid] = m; ss[tid] = s; __syncthreads();
    #pragma unroll
    for (int off = 128; off > 0; off >>= 1) {
        if (tid < off) {
            float m2 = sm[tid + off], s2 = ss[tid + off];
            float M = fmaxf(sm[tid], m2);
            ss[tid] = ss[tid] * expf(sm[tid] - M) + s2 * expf(m2 - M);
            sm[tid] = M;
        }
        __syncthreads();
    }
    if (tid == 0)
        nll[row] = sm[0] + logf(ss[0]) - lr[targets[row]];
}

__global__ void loss_kernel(const float* __restrict__ nll, float* __restrict__ dst,
                            int nextra) {
    __shared__ float red[256];
    int tid = threadIdx.x;
    float s = 0.f;
    for (int i = tid; i < BT; i += 256) s += nll[i];
    red[tid] = s; __syncthreads();
    #pragma unroll
    for (int off = 128; off > 0; off >>= 1) {
        if (tid < off) red[tid] += red[tid + off];
        __syncthreads();
    }
    if (tid == 0) {
        float loss = red[0] * (1.f / BT);
        for (int i = 0; i < nextra; i++) dst[i] = loss;
    }
}

// ---------------- launch ----------------
extern "C" void kernel_launch(void* const* d_in, const int* in_sizes, int n_in,
                              void* d_out, int out_size) {
    const int*   idx     = (const int*)  d_in[0];
    const int*   targets = (const int*)  d_in[1];
    const float* tok_emb = (const float*)d_in[2];
    const float* pos_emb = (const float*)d_in[3];
    const float* Wq      = (const float*)d_in[4];
    const float* Wk      = (const float*)d_in[5];
    const float* Wv      = (const float*)d_in[6];
    const float* Wo      = (const float*)d_in[7];
    const float* bo      = (const float*)d_in[8];
    const float* ln1_g   = (const float*)d_in[9];
    const float* ln1_b   = (const float*)d_in[10];
    const float* ln2_g   = (const float*)d_in[11];
    const float* ln2_b   = (const float*)d_in[12];
    const float* W1      = (const float*)d_in[13];
    const float* b1      = (const float*)d_in[14];
    const float* W2      = (const float*)d_in[15];
    const float* b2      = (const float*)d_in[16];
    const float* Wlm     = (const float*)d_in[17];
    const float* blm     = (const float*)d_in[18];

    float *x, *h, *q, *k, *v, *o, *ff, *att, *nll;
    cudaGetSymbolAddress((void**)&x,   g_x);
    cudaGetSymbolAddress((void**)&h,   g_h);
    cudaGetSymbolAddress((void**)&q,   g_q);
    cudaGetSymbolAddress((void**)&k,   g_k);
    cudaGetSymbolAddress((void**)&v,   g_v);
    cudaGetSymbolAddress((void**)&o,   g_o);
    cudaGetSymbolAddress((void**)&ff,  g_ff);
    cudaGetSymbolAddress((void**)&att, g_att);
    cudaGetSymbolAddress((void**)&nll, g_nll);

    embed_kernel<<<(BT * D + 255) / 256, 256>>>(idx, tok_emb, pos_emb, x);

    dim3 gD(BT / 128, (D  + 127) / 128);      // 32 x 6
    dim3 gF(BT / 128, (FF + 127) / 128);      // 32 x 24
    dim3 gV(BT / 128, (VV + 127) / 128);      // 32 x 393

    for (int l = 0; l < NL; l++) {
        const float* wq = Wq + (size_t)l * D * D;
        const float* wk = Wk + (size_t)l * D * D;
        const float* wv = Wv + (size_t)l * D * D;
        const float* wo = Wo + (size_t)l * D * D;
        const float* w1 = W1 + (size_t)l * D * FF;
        const float* w2 = W2 + (size_t)l * FF * D;

        ln_kernel<<<BT, 256>>>(x, ln1_g + (size_t)l * D, ln1_b + (size_t)l * D, h);
        gemm_tf32<<<gD, 256>>>(h, wq, nullptr, nullptr, q, BT, D, D, 0);
        gemm_tf32<<<gD, 256>>>(h, wk, nullptr, nullptr, k, BT, D, D, 0);
        gemm_tf32<<<gD, 256>>>(h, wv, nullptr, nullptr, v, BT, D, D, 0);

        attn_scores<<<dim3(TT / 64, TT / 64, BH), 256>>>(q, k, att);
        attn_softmax<<<BH * TT, 256>>>(att);
        attn_pv<<<dim3(TT / 64, BH), 256>>>(att, v, o);

        gemm_tf32<<<gD, 256>>>(o, wo, bo + (size_t)l * D, x, x, BT, D, D, 0);

        ln_kernel<<<BT, 256>>>(x, ln2_g + (size_t)l * D, ln2_b + (size_t)l * D, h);
        gemm_tf32<<<gF, 256>>>(h, w1, b1 + (size_t)l * FF, nullptr, ff, BT, FF, D, 1);
        gemm_tf32<<<gD, 256>>>(ff, w2, b2 + (size_t)l * D, x, x, BT, D, FF, 0);
    }

    float* logits = (float*)d_out;
    gemm_tf32<<<gV, 256>>>(x, Wlm, blm, nullptr, logits, BT, VV, D, 0);

    long long btv = (long long)BT * VV;
    if ((long long)out_size > btv) {
        nll_kernel<<<BT, 256>>>(logits, targets, nll);
        loss_kernel<<<1, 256>>>(nll, logits + btv, (int)((long long)out_size - btv));
    }
}

// round 3
// speedup vs baseline: 2.7025x; 1.6887x over previous
#include <cuda_runtime.h>
#include <cuda_bf16.h>
#include <float.h>
#include <math.h>

// ---------------- problem constants ----------------
#define NL   12
#define D    768
#define NH   12
#define HD   64
#define VV   50257
#define BB   4
#define TT   1024
#define BT   (BB*TT)          // 4096
#define FF   (4*D)            // 3072
#define BH   (BB*NH)          // 48
#define EPSF 1e-5f
#define SCALE 0.125f          // HD^-0.5

// ---------------- scratch (device globals; no runtime alloc) ----------------
__device__ float g_x[BT*D];
__device__ float g_h[BT*D];
__device__ float g_q[BT*D];
__device__ float g_k[BT*D];
__device__ float g_v[BT*D];
__device__ float g_o[BT*D];
__device__ float g_ff[BT*FF];
__device__ float g_att[(size_t)BH*TT*TT];   // 201 MB
__device__ float g_nll[BT];

// ---------------- tf32 / async helpers ----------------
__device__ __forceinline__ unsigned f2tf(float x) {
    unsigned r;
    asm("cvt.rna.tf32.f32 %0, %1;" : "=r"(r) : "f"(x));
    return r;
}
__device__ __forceinline__ void mma_tf32(float* d, const unsigned* a, const unsigned* b) {
    asm volatile(
        "mma.sync.aligned.m16n8k8.row.col.f32.tf32.tf32.f32 "
        "{%0,%1,%2,%3}, {%4,%5,%6,%7}, {%8,%9}, {%0,%1,%2,%3};"
        : "+f"(d[0]), "+f"(d[1]), "+f"(d[2]), "+f"(d[3])
        : "r"(a[0]), "r"(a[1]), "r"(a[2]), "r"(a[3]), "r"(b[0]), "r"(b[1]));
}
__device__ __forceinline__ void cp16(void* s, const void* g) {
    unsigned sa = (unsigned)__cvta_generic_to_shared(s);
    asm volatile("cp.async.cg.shared.global [%0], [%1], 16;" :: "r"(sa), "l"(g));
}
__device__ __forceinline__ void cp4z(void* s, const void* g, int srcbytes) {
    unsigned sa = (unsigned)__cvta_generic_to_shared(s);
    asm volatile("cp.async.ca.shared.global [%0], [%1], 4, %2;"
                 :: "r"(sa), "l"(g), "r"(srcbytes));
}
#define CP_COMMIT() asm volatile("cp.async.commit_group;")
#define CP_WAIT1()  asm volatile("cp.async.wait_group 1;")

// ---------------- embedding ----------------
__global__ void embed_kernel(const int* __restrict__ idx,
                             const float* __restrict__ tok,
                             const float* __restrict__ pos,
                             float* __restrict__ x) {
    int i = blockIdx.x * 256 + threadIdx.x;
    if (i >= BT * D) return;
    int row = i / D;
    int d   = i - row * D;
    int t   = row & (TT - 1);
    x[i] = tok[(size_t)idx[row] * D + d] + pos[(size_t)t * D + d];
}

// ---------------- layernorm (one block per row) ----------------
__global__ void ln_kernel(const float* __restrict__ x,
                          const float* __restrict__ g,
                          const float* __restrict__ b,
                          float* __restrict__ out) {
    int row = blockIdx.x;
    const float* xr = x + (size_t)row * D;
    __shared__ float sx[D];
    __shared__ float red[256];
    int tid = threadIdx.x;

    float s = 0.f;
    for (int i = tid; i < D; i += 256) { float t = xr[i]; sx[i] = t; s += t; }
    red[tid] = s; __syncthreads();
    #pragma unroll
    for (int off = 128; off > 0; off >>= 1) {
        if (tid < off) red[tid] += red[tid + off];
        __syncthreads();
    }
    float mean = red[0] * (1.f / D);
    __syncthreads();

    float s2 = 0.f;
    for (int i = tid; i < D; i += 256) { float t = sx[i] - mean; s2 += t * t; }
    red[tid] = s2; __syncthreads();
    #pragma unroll
    for (int off = 128; off > 0; off >>= 1) {
        if (tid < off) red[tid] += red[tid + off];
        __syncthreads();
    }
    float rstd = rsqrtf(red[0] * (1.f / D) + EPSF);

    float* orow = out + (size_t)row * D;
    for (int i = tid; i < D; i += 256)
        orow[i] = (sx[i] - mean) * rstd * g[i] + b[i];
}

// ---------------- TF32 tensor-core GEMM, 2-stage cp.async pipeline ----------------
// C[M,N] = A[M,K] @ B[K,N] (+bias) (+resid) (relu?)
// Block tile 128x128x32, 128 threads = 4 warps as 2(M) x 2(N), warp tile 64x64.
// Smem: A stored [m][k] stride 36 (f32), B stored [k][n] stride 132; 2 stages.
#define AK    36
#define BN    132
#define ASTG  (128*AK)          // floats per A stage
#define BSTG  (32*BN)           // floats per B stage
#define BOFF  (2*ASTG)
#define GSMEM ((2*ASTG + 2*BSTG) * 4)   // 70656 bytes

__global__ __launch_bounds__(128)
void gemm_tf32(const float* __restrict__ A, const float* __restrict__ Bm,
               const float* __restrict__ bias, const float* __restrict__ resid,
               float* __restrict__ C, int M, int N, int K, int relu) {
    extern __shared__ float smem[];

    const int tid  = threadIdx.x;
    const int lane = tid & 31;
    const int wid  = tid >> 5;
    const int warpM = (wid >> 1) * 64;   // 0,64
    const int warpN = (wid & 1) * 64;    // 0,64
    const int gm = blockIdx.x * 128;
    const int gn = blockIdx.y * 128;
    const int lt = lane & 3;
    const int lg = lane >> 2;
    const bool alignedB = ((N & 3) == 0);

    float acc[4][8][4];
    #pragma unroll
    for (int mi = 0; mi < 4; mi++)
        #pragma unroll
        for (int nj = 0; nj < 8; nj++)
            #pragma unroll
            for (int r = 0; r < 4; r++) acc[mi][nj][r] = 0.f;

    const int nch = K >> 5;

    // ---- tile loader (cp.async) ----
    auto load_tiles = [&](int k0, int stage) {
        float* As = smem + stage * ASTG;
        float* Bs = smem + BOFF + stage * BSTG;
        // A: 128x32, 16B chunks; always in-bounds (M mult of 128, K mult of 32)
        #pragma unroll
        for (int i = 0; i < 8; i++) {
            int c  = tid + i * 128;
            int m  = c >> 3;
            int k4 = (c & 7) << 2;
            cp16(As + m * AK + k4, A + (size_t)(gm + m) * K + k0 + k4);
        }
        if (alignedB) {
            #pragma unroll
            for (int i = 0; i < 8; i++) {
                int c  = tid + i * 128;
                int kr = c >> 5;
                int n4 = (c & 31) << 2;
                cp16(Bs + kr * BN + n4, Bm + (size_t)(k0 + kr) * N + gn + n4);
            }
        } else {
            #pragma unroll
            for (int i = 0; i < 32; i++) {
                int c  = tid + i * 128;          // 0..4095 scalars
                int kr = c >> 7;
                int n  = c & 127;
                int col = gn + n;
                cp4z(Bs + kr * BN + n, Bm + (size_t)(k0 + kr) * N + col,
                     (col < N) ? 4 : 0);
            }
        }
    };

    load_tiles(0, 0);
    CP_COMMIT();

    for (int ch = 0; ch < nch; ch++) {
        int stage = ch & 1;
        if (ch + 1 < nch) load_tiles((ch + 1) << 5, stage ^ 1);
        CP_COMMIT();
        CP_WAIT1();
        __syncthreads();

        const float* Asb = smem + stage * ASTG;
        const float* Bsb = smem + BOFF + stage * BSTG;

        #pragma unroll
        for (int kk = 0; kk < 32; kk += 8) {
            unsigned a[4][4], b[8][2];
            #pragma unroll
            for (int mi = 0; mi < 4; mi++) {
                const float* p0 = Asb + (warpM + mi * 16 + lg) * AK + kk;
                const float* p1 = p0 + 8 * AK;
                a[mi][0] = f2tf(p0[lt]);
                a[mi][1] = f2tf(p1[lt]);
                a[mi][2] = f2tf(p0[lt + 4]);
                a[mi][3] = f2tf(p1[lt + 4]);
            }
            #pragma unroll
            for (int nj = 0; nj < 8; nj++) {
                int nc = warpN + nj * 8 + lg;
                b[nj][0] = f2tf(Bsb[(kk + lt) * BN + nc]);
                b[nj][1] = f2tf(Bsb[(kk + lt + 4) * BN + nc]);
            }
            #pragma unroll
            for (int mi = 0; mi < 4; mi++)
                #pragma unroll
                for (int nj = 0; nj < 8; nj++)
                    mma_tf32(acc[mi][nj], a[mi], b[nj]);
        }
        __syncthreads();
    }

    // ---- epilogue ----
    #pragma unroll
    for (int mi = 0; mi < 4; mi++) {
        int r0 = gm + warpM + mi * 16 + lg;
        #pragma unroll
        for (int nj = 0; nj < 8; nj++) {
            int c0 = gn + warpN + nj * 8 + (lt << 1);
            #pragma unroll
            for (int r = 0; r < 4; r++) {
                int rowg = r0 + ((r >> 1) << 3);
                int colg = c0 + (r & 1);
                if (colg < N) {
                    float v = acc[mi][nj][r];
                    if (bias)  v += bias[colg];
                    if (resid) v += resid[(size_t)rowg * N + colg];
                    if (relu)  v = fmaxf(v, 0.f);
                    C[(size_t)rowg * N + colg] = v;
                }
            }
        }
    }
}

// ---------------- attention: scores = scale * Q K^T with causal mask ----------------
__global__ void attn_scores(const float* __restrict__ q, const float* __restrict__ k,
                            float* __restrict__ att) {
    int tb = blockIdx.x, sb = blockIdx.y, bh = blockIdx.z;
    if (sb > tb) return;
    int b = bh / NH, h = bh % NH;

    __shared__ float Qs[64][65];
    __shared__ float Ks[64][65];
    int tid = threadIdx.x;

    const float* qb = q + (size_t)b * TT * D + (size_t)h * HD;
    const float* kb = k + (size_t)b * TT * D + (size_t)h * HD;
    #pragma unroll
    for (int i = 0; i < 16; i++) {
        int idx = tid + i * 256;
        int m = idx >> 6, d = idx & 63;
        Qs[d][m] = qb[(size_t)(tb * 64 + m) * D + d];
        Ks[d][m] = kb[(size_t)(sb * 64 + m) * D + d];
    }
    __syncthreads();

    int tx = tid & 15, ty = tid >> 4;
    int m0 = ty * 4, n0 = tx * 4;
    float acc[4][4];
    #pragma unroll
    for (int i = 0; i < 4; i++)
        #pragma unroll
        for (int j = 0; j < 4; j++) acc[i][j] = 0.f;

    #pragma unroll
    for (int d = 0; d < 64; d++) {
        float a[4], bv[4];
        #pragma unroll
        for (int i = 0; i < 4; i++) a[i]  = Qs[d][m0 + i];
        #pragma unroll
        for (int j = 0; j < 4; j++) bv[j] = Ks[d][n0 + j];
        #pragma unroll
        for (int i = 0; i < 4; i++)
            #pragma unroll
            for (int j = 0; j < 4; j++)
                acc[i][j] = fmaf(a[i], bv[j], acc[i][j]);
    }

    float* out = att + ((size_t)bh * TT + (size_t)tb * 64) * TT + (size_t)sb * 64;
    #pragma unroll
    for (int i = 0; i < 4; i++) {
        int t = tb * 64 + m0 + i;
        #pragma unroll
        for (int j = 0; j < 4; j++) {
            int s = sb * 64 + n0 + j;
            out[(size_t)(m0 + i) * TT + n0 + j] =
                (s <= t) ? acc[i][j] * SCALE : -3.402823466e38f;
        }
    }
}

// ---------------- attention row softmax ----------------
__global__ void attn_softmax(float* __restrict__ att) {
    int row = blockIdx.x;
    int t = row & (TT - 1);
    float* p = att + (size_t)row * TT;
    int L = ((t >> 6) + 1) << 6;
    int tid = threadIdx.x;

    float m = -FLT_MAX, s = 0.f;
    for (int i = tid; i < L; i += 256) {
        float x = p[i];
        if (x > m) { s = s * expf(m - x) + 1.f; m = x; }
        else        s += expf(x - m);
    }
    __shared__ float sm[256], ss[256];
    sm[tid] = m; ss[tid] = s; __syncthreads();
    #pragma unroll
    for (int off = 128; off > 0; off >>= 1) {
        if (tid < off) {
            float m2 = sm[tid + off], s2 = ss[tid + off];
            float M = fmaxf(sm[tid], m2);
            ss[tid] = ss[tid] * expf(sm[tid] - M) + s2 * expf(m2 - M);
            sm[tid] = M;
        }
        __syncthreads();
    }
    float gm = sm[0];
    float inv = 1.f / ss[0];
    for (int i = tid; i < L; i += 256)
        p[i] = expf(p[i] - gm) * inv;
}

// ---------------- attention PV ----------------
__global__ void attn_pv(const float* __restrict__ att, const float* __restrict__ v,
                        float* __restrict__ o) {
    int tb = blockIdx.x, bh = blockIdx.y;
    int b = bh / NH, h = bh % NH;

    __shared__ float Ps[32][68];
    __shared__ float Vs[32][64];
    int tid = threadIdx.x;
    int tx = tid & 15, ty = tid >> 4;
    int m0 = ty * 4, n0 = tx * 4;

    float acc[4][4];
    #pragma unroll
    for (int i = 0; i < 4; i++)
        #pragma unroll
        for (int j = 0; j < 4; j++) acc[i][j] = 0.f;

    const float* arow = att + ((size_t)bh * TT + (size_t)tb * 64) * TT;
    const float* vb = v + (size_t)b * TT * D + (size_t)h * HD;
    int Smax = (tb + 1) * 64;

    for (int s0 = 0; s0 < Smax; s0 += 32) {
        #pragma unroll
        for (int i = 0; i < 8; i++) {
            int idx = tid + i * 256;
            int m = idx >> 5, kk = idx & 31;
            Ps[kk][m] = arow[(size_t)m * TT + s0 + kk];
        }
        #pragma unroll
        for (int i = 0; i < 8; i++) {
            int idx = tid + i * 256;
            int kk = idx >> 6, n = idx & 63;
            Vs[kk][n] = vb[(size_t)(s0 + kk) * D + n];
        }
        __syncthreads();
        #pragma unroll
        for (int kk = 0; kk < 32; kk++) {
            float a[4], bv[4];
            #pragma unroll
            for (int i = 0; i < 4; i++) a[i]  = Ps[kk][m0 + i];
            #pragma unroll
            for (int j = 0; j < 4; j++) bv[j] = Vs[kk][n0 + j];
            #pragma unroll
            for (int i = 0; i < 4; i++)
                #pragma unroll
                for (int j = 0; j < 4; j++)
                    acc[i][j] = fmaf(a[i], bv[j], acc[i][j]);
        }
        __syncthreads();
    }

    float* ob = o + (size_t)(b * TT + tb * 64) * D + (size_t)h * HD;
    #pragma unroll
    for (int i = 0; i < 4; i++)
        #pragma unroll
        for (int j = 0; j < 4; j++)
            ob[(size_t)(m0 + i) * D + n0 + j] = acc[i][j];
}

// ---------------- per-row NLL over vocab ----------------
__global__ void nll_kernel(const float* __restrict__ logits,
                           const int* __restrict__ targets,
                           float* __restrict__ nll) {
    int row = blockIdx.x;
    const float* lr = logits + (size_t)row * VV;
    int tid = threadIdx.x;

    float m = -FLT_MAX, s = 0.f;
    for (int i = tid; i < VV; i += 256) {
        float x = lr[i];
        if (x > m) { s = s * expf(m - x) + 1.f; m = x; }
        else        s += expf(x - m);
    }
    __shared__ float sm[256], ss[256];
    sm[tid] = m; ss[tid] = s; __syncthreads();
    #pragma unroll
    for (int off = 128; off > 0; off >>= 1) {
        if (tid < off) {
            float m2 = sm[tid + off], s2 = ss[tid + off];
            float M = fmaxf(sm[tid], m2);
            ss[tid] = ss[tid] * expf(sm[tid] - M) + s2 * expf(m2 - M);
            sm[tid] = M;
        }
        __syncthreads();
    }
    if (tid == 0)
        nll[row] = sm[0] + logf(ss[0]) - lr[targets[row]];
}

__global__ void loss_kernel(const float* __restrict__ nll, float* __restrict__ dst,
                            int nextra) {
    __shared__ float red[256];
    int tid = threadIdx.x;
    float s = 0.f;
    for (int i = tid; i < BT; i += 256) s += nll[i];
    red[tid] = s; __syncthreads();
    #pragma unroll
    for (int off = 128; off > 0; off >>= 1) {
        if (tid < off) red[tid] += red[tid + off];
        __syncthreads();
    }
    if (tid == 0) {
        float loss = red[0] * (1.f / BT);
        for (int i = 0; i < nextra; i++) dst[i] = loss;
    }
}

// ---------------- launch ----------------
extern "C" void kernel_launch(void* const* d_in, const int* in_sizes, int n_in,
                              void* d_out, int out_size) {
    const int*   idx     = (const int*)  d_in[0];
    const int*   targets = (const int*)  d_in[1];
    const float* tok_emb = (const float*)d_in[2];
    const float* pos_emb = (const float*)d_in[3];
    const float* Wq      = (const float*)d_in[4];
    const float* Wk      = (const float*)d_in[5];
    const float* Wv      = (const float*)d_in[6];
    const float* Wo      = (const float*)d_in[7];
    const float* bo      = (const float*)d_in[8];
    const float* ln1_g   = (const float*)d_in[9];
    const float* ln1_b   = (const float*)d_in[10];
    const float* ln2_g   = (const float*)d_in[11];
    const float* ln2_b   = (const float*)d_in[12];
    const float* W1      = (const float*)d_in[13];
    const float* b1      = (const float*)d_in[14];
    const float* W2      = (const float*)d_in[15];
    const float* b2      = (const float*)d_in[16];
    const float* Wlm     = (const float*)d_in[17];
    const float* blm     = (const float*)d_in[18];

    float *x, *h, *q, *k, *v, *o, *ff, *att, *nll;
    cudaGetSymbolAddress((void**)&x,   g_x);
    cudaGetSymbolAddress((void**)&h,   g_h);
    cudaGetSymbolAddress((void**)&q,   g_q);
    cudaGetSymbolAddress((void**)&k,   g_k);
    cudaGetSymbolAddress((void**)&v,   g_v);
    cudaGetSymbolAddress((void**)&o,   g_o);
    cudaGetSymbolAddress((void**)&ff,  g_ff);
    cudaGetSymbolAddress((void**)&att, g_att);
    cudaGetSymbolAddress((void**)&nll, g_nll);

    cudaFuncSetAttribute(gemm_tf32, cudaFuncAttributeMaxDynamicSharedMemorySize, GSMEM);

    embed_kernel<<<(BT * D + 255) / 256, 256>>>(idx, tok_emb, pos_emb, x);

    dim3 gD(BT / 128, (D  + 127) / 128);      // 32 x 6
    dim3 gF(BT / 128, (FF + 127) / 128);      // 32 x 24
    dim3 gV(BT / 128, (VV + 127) / 128);      // 32 x 393

    for (int l = 0; l < NL; l++) {
        const float* wq = Wq + (size_t)l * D * D;
        const float* wk = Wk + (size_t)l * D * D;
        const float* wv = Wv + (size_t)l * D * D;
        const float* wo = Wo + (size_t)l * D * D;
        const float* w1 = W1 + (size_t)l * D * FF;
        const float* w2 = W2 + (size_t)l * FF * D;

        ln_kernel<<<BT, 256>>>(x, ln1_g + (size_t)l * D, ln1_b + (size_t)l * D, h);
        gemm_tf32<<<gD, 128, GSMEM>>>(h, wq, nullptr, nullptr, q, BT, D, D, 0);
        gemm_tf32<<<gD, 128, GSMEM>>>(h, wk, nullptr, nullptr, k, BT, D, D, 0);
        gemm_tf32<<<gD, 128, GSMEM>>>(h, wv, nullptr, nullptr, v, BT, D, D, 0);

        attn_scores<<<dim3(TT / 64, TT / 64, BH), 256>>>(q, k, att);
        attn_softmax<<<BH * TT, 256>>>(att);
        attn_pv<<<dim3(TT / 64, BH), 256>>>(att, v, o);

        gemm_tf32<<<gD, 128, GSMEM>>>(o, wo, bo + (size_t)l * D, x, x, BT, D, D, 0);

        ln_kernel<<<BT, 256>>>(x, ln2_g + (size_t)l * D, ln2_b + (size_t)l * D, h);
        gemm_tf32<<<gF, 128, GSMEM>>>(h, w1, b1 + (size_t)l * FF, nullptr, ff, BT, FF, D, 1);
        gemm_tf32<<<gD, 128, GSMEM>>>(ff, w2, b2 + (size_t)l * D, x, x, BT, D, FF, 0);
    }

    float* logits = (float*)d_out;
    gemm_tf32<<<gV, 128, GSMEM>>>(x, Wlm, blm, nullptr, logits, BT, VV, D, 0);

    long long btv = (long long)BT * VV;
    if ((long long)out_size > btv) {
        nll_kernel<<<BT, 256>>>(logits, targets, nll);
        loss_kernel<<<1, 256>>>(nll, logits + btv, (int)((long long)out_size - btv));
    }
}

// round 4
// speedup vs baseline: 3.0414x; 1.1254x over previous
#include <cuda_runtime.h>
#include <cuda_bf16.h>
#include <float.h>
#include <math.h>

// ---------------- problem constants ----------------
#define NL   12
#define D    768
#define NH   12
#define HD   64
#define VV   50257
#define BB   4
#define TT   1024
#define BT   (BB*TT)          // 4096
#define FF   (4*D)            // 3072
#define BH   (BB*NH)          // 48
#define EPSF 1e-5f
#define SCALE 0.125f          // HD^-0.5

// ---------------- scratch (device globals; no runtime alloc) ----------------
__device__ float g_x[BT*D];
__device__ float g_h[BT*D];
__device__ float g_q[BT*D];
__device__ float g_k[BT*D];
__device__ float g_v[BT*D];
__device__ float g_o[BT*D];
__device__ float g_ff[BT*FF];
__device__ float g_att[(size_t)BH*TT*TT];   // 201 MB
__device__ float g_nll[BT];
// pre-rounded (tf32) weights
__device__ float g_rwq[NL*D*D];
__device__ float g_rwk[NL*D*D];
__device__ float g_rwv[NL*D*D];
__device__ float g_rwo[NL*D*D];
__device__ float g_rw1[(size_t)NL*D*FF];
__device__ float g_rw2[(size_t)NL*FF*D];
__device__ float g_rwlm[(size_t)D*VV];

// ---------------- tf32 / async helpers ----------------
__device__ __forceinline__ unsigned f2tf(float x) {
    unsigned r;
    asm("cvt.rna.tf32.f32 %0, %1;" : "=r"(r) : "f"(x));
    return r;
}
__device__ __forceinline__ float tf32f(float x) { return __uint_as_float(f2tf(x)); }

__device__ __forceinline__ void mma_tf32(float* d, const unsigned* a, const unsigned* b) {
    asm volatile(
        "mma.sync.aligned.m16n8k8.row.col.f32.tf32.tf32.f32 "
        "{%0,%1,%2,%3}, {%4,%5,%6,%7}, {%8,%9}, {%0,%1,%2,%3};"
        : "+f"(d[0]), "+f"(d[1]), "+f"(d[2]), "+f"(d[3])
        : "r"(a[0]), "r"(a[1]), "r"(a[2]), "r"(a[3]), "r"(b[0]), "r"(b[1]));
}
__device__ __forceinline__ void cp16(void* s, const void* g) {
    unsigned sa = (unsigned)__cvta_generic_to_shared(s);
    asm volatile("cp.async.cg.shared.global [%0], [%1], 16;" :: "r"(sa), "l"(g));
}
__device__ __forceinline__ void cp4z(void* s, const void* g, int srcbytes) {
    unsigned sa = (unsigned)__cvta_generic_to_shared(s);
    asm volatile("cp.async.ca.shared.global [%0], [%1], 4, %2;"
                 :: "r"(sa), "l"(g), "r"(srcbytes));
}
#define CP_COMMIT() asm volatile("cp.async.commit_group;")
#define CP_WAIT1()  asm volatile("cp.async.wait_group 1;")

// ---------------- tf32 rounding pass (grid-stride) ----------------
__global__ void round_kernel(const float* __restrict__ in, float* __restrict__ out,
                             long long n) {
    long long i = (long long)blockIdx.x * blockDim.x + threadIdx.x;
    long long stride = (long long)gridDim.x * blockDim.x;
    for (; i < n; i += stride) out[i] = tf32f(in[i]);
}

// ---------------- embedding ----------------
__global__ void embed_kernel(const int* __restrict__ idx,
                             const float* __restrict__ tok,
                             const float* __restrict__ pos,
                             float* __restrict__ x) {
    int i = blockIdx.x * 256 + threadIdx.x;
    if (i >= BT * D) return;
    int row = i / D;
    int d   = i - row * D;
    int t   = row & (TT - 1);
    x[i] = tok[(size_t)idx[row] * D + d] + pos[(size_t)t * D + d];
}

// ---------------- layernorm (output pre-rounded to tf32) ----------------
__global__ void ln_kernel(const float* __restrict__ x,
                          const float* __restrict__ g,
                          const float* __restrict__ b,
                          float* __restrict__ out) {
    int row = blockIdx.x;
    const float* xr = x + (size_t)row * D;
    __shared__ float sx[D];
    __shared__ float red[256];
    int tid = threadIdx.x;

    float s = 0.f;
    for (int i = tid; i < D; i += 256) { float t = xr[i]; sx[i] = t; s += t; }
    red[tid] = s; __syncthreads();
    #pragma unroll
    for (int off = 128; off > 0; off >>= 1) {
        if (tid < off) red[tid] += red[tid + off];
        __syncthreads();
    }
    float mean = red[0] * (1.f / D);
    __syncthreads();

    float s2 = 0.f;
    for (int i = tid; i < D; i += 256) { float t = sx[i] - mean; s2 += t * t; }
    red[tid] = s2; __syncthreads();
    #pragma unroll
    for (int off = 128; off > 0; off >>= 1) {
        if (tid < off) red[tid] += red[tid + off];
        __syncthreads();
    }
    float rstd = rsqrtf(red[0] * (1.f / D) + EPSF);

    float* orow = out + (size_t)row * D;
    for (int i = tid; i < D; i += 256)
        orow[i] = tf32f((sx[i] - mean) * rstd * g[i] + b[i]);
}

// ---------------- TF32 tensor-core GEMM, cvt-free inner loop ----------------
// C[M,N] = A[M,K] @ B[K,N] (+bias) (+resid) (relu?) (round output to tf32?)
// A and B must be pre-rounded to tf32 bit patterns.
// Block tile 128x64x32, 128 threads = 4 warps as 2(M) x 2(N), warp tile 64x32.
#define AK    36
#define BN2   68
#define ASTG  (128*AK)          // floats per A stage (4608)
#define BSTG  (32*BN2)          // floats per B stage (2176)
#define BOFF  (2*ASTG)
#define GSMEM ((2*ASTG + 2*BSTG) * 4)   // 54272 bytes

__global__ __launch_bounds__(128, 3)
void gemm_tf32(const float* __restrict__ A, const float* __restrict__ Bm,
               const float* __restrict__ bias, const float* __restrict__ resid,
               float* __restrict__ C, int M, int N, int K, int relu, int roundC) {
    extern __shared__ float smem[];

    const int tid  = threadIdx.x;
    const int lane = tid & 31;
    const int wid  = tid >> 5;
    const int warpM = (wid >> 1) * 64;   // 0,64
    const int warpN = (wid & 1) * 32;    // 0,32
    const int gm = blockIdx.x * 128;
    const int gn = blockIdx.y * 64;
    const int lt = lane & 3;
    const int lg = lane >> 2;
    const bool alignedB = ((N & 3) == 0);

    float acc[4][4][4];
    #pragma unroll
    for (int mi = 0; mi < 4; mi++)
        #pragma unroll
        for (int nj = 0; nj < 4; nj++)
            #pragma unroll
            for (int r = 0; r < 4; r++) acc[mi][nj][r] = 0.f;

    const int nch = K >> 5;

    auto load_tiles = [&](int k0, int stage) {
        float* As = smem + stage * ASTG;
        float* Bs = smem + BOFF + stage * BSTG;
        // A: 128x32 (16B chunks; M,K multiples of 128/32)
        #pragma unroll
        for (int i = 0; i < 8; i++) {
            int c  = tid + i * 128;        // 0..1023
            int m  = c >> 3;
            int k4 = (c & 7) << 2;
            cp16(As + m * AK + k4, A + (size_t)(gm + m) * K + k0 + k4);
        }
        // B: 32x64
        if (alignedB) {
            #pragma unroll
            for (int i = 0; i < 4; i++) {
                int c  = tid + i * 128;    // 0..511
                int kr = c >> 4;
                int n4 = (c & 15) << 2;
                cp16(Bs + kr * BN2 + n4, Bm + (size_t)(k0 + kr) * N + gn + n4);
            }
        } else {
            #pragma unroll
            for (int i = 0; i < 16; i++) {
                int c  = tid + i * 128;    // 0..2047
                int kr = c >> 6;
                int n  = c & 63;
                int col = gn + n;
                cp4z(Bs + kr * BN2 + n, Bm + (size_t)(k0 + kr) * N + col,
                     (col < N) ? 4 : 0);
            }
        }
    };

    load_tiles(0, 0);
    CP_COMMIT();

    for (int ch = 0; ch < nch; ch++) {
        int stage = ch & 1;
        if (ch + 1 < nch) load_tiles((ch + 1) << 5, stage ^ 1);
        CP_COMMIT();
        CP_WAIT1();
        __syncthreads();

        const float* Asb = smem + stage * ASTG;
        const float* Bsb = smem + BOFF + stage * BSTG;

        #pragma unroll
        for (int kk = 0; kk < 32; kk += 8) {
            unsigned a[4][4], b[4][2];
            #pragma unroll
            for (int mi = 0; mi < 4; mi++) {
                const float* p0 = Asb + (warpM + mi * 16 + lg) * AK + kk;
                const float* p1 = p0 + 8 * AK;
                a[mi][0] = __float_as_uint(p0[lt]);
                a[mi][1] = __float_as_uint(p1[lt]);
                a[mi][2] = __float_as_uint(p0[lt + 4]);
                a[mi][3] = __float_as_uint(p1[lt + 4]);
            }
            #pragma unroll
            for (int nj = 0; nj < 4; nj++) {
                int nc = warpN + nj * 8 + lg;
                b[nj][0] = __float_as_uint(Bsb[(kk + lt) * BN2 + nc]);
                b[nj][1] = __float_as_uint(Bsb[(kk + lt + 4) * BN2 + nc]);
            }
            #pragma unroll
            for (int mi = 0; mi < 4; mi++)
                #pragma unroll
                for (int nj = 0; nj < 4; nj++)
                    mma_tf32(acc[mi][nj], a[mi], b[nj]);
        }
        __syncthreads();
    }

    // ---- epilogue ----
    #pragma unroll
    for (int mi = 0; mi < 4; mi++) {
        int r0 = gm + warpM + mi * 16 + lg;
        #pragma unroll
        for (int nj = 0; nj < 4; nj++) {
            int c0 = gn + warpN + nj * 8 + (lt << 1);
            #pragma unroll
            for (int r = 0; r < 4; r++) {
                int rowg = r0 + ((r >> 1) << 3);
                int colg = c0 + (r & 1);
                if (colg < N) {
                    float v = acc[mi][nj][r];
                    if (bias)   v += bias[colg];
                    if (resid)  v += resid[(size_t)rowg * N + colg];
                    if (relu)   v = fmaxf(v, 0.f);
                    if (roundC) v = tf32f(v);
                    C[(size_t)rowg * N + colg] = v;
                }
            }
        }
    }
}

// ---------------- attention: scores = scale * Q K^T with causal mask ----------------
__global__ void attn_scores(const float* __restrict__ q, const float* __restrict__ k,
                            float* __restrict__ att) {
    int tb = blockIdx.x, sb = blockIdx.y, bh = blockIdx.z;
    if (sb > tb) return;
    int b = bh / NH, h = bh % NH;

    __shared__ float Qs[64][65];
    __shared__ float Ks[64][65];
    int tid = threadIdx.x;

    const float* qb = q + (size_t)b * TT * D + (size_t)h * HD;
    const float* kb = k + (size_t)b * TT * D + (size_t)h * HD;
    #pragma unroll
    for (int i = 0; i < 16; i++) {
        int idx = tid + i * 256;
        int m = idx >> 6, d = idx & 63;
        Qs[d][m] = qb[(size_t)(tb * 64 + m) * D + d];
        Ks[d][m] = kb[(size_t)(sb * 64 + m) * D + d];
    }
    __syncthreads();

    int tx = tid & 15, ty = tid >> 4;
    int m0 = ty * 4, n0 = tx * 4;
    float acc[4][4];
    #pragma unroll
    for (int i = 0; i < 4; i++)
        #pragma unroll
        for (int j = 0; j < 4; j++) acc[i][j] = 0.f;

    #pragma unroll
    for (int d = 0; d < 64; d++) {
        float a[4], bv[4];
        #pragma unroll
        for (int i = 0; i < 4; i++) a[i]  = Qs[d][m0 + i];
        #pragma unroll
        for (int j = 0; j < 4; j++) bv[j] = Ks[d][n0 + j];
        #pragma unroll
        for (int i = 0; i < 4; i++)
            #pragma unroll
            for (int j = 0; j < 4; j++)
                acc[i][j] = fmaf(a[i], bv[j], acc[i][j]);
    }

    float* out = att + ((size_t)bh * TT + (size_t)tb * 64) * TT + (size_t)sb * 64;
    #pragma unroll
    for (int i = 0; i < 4; i++) {
        int t = tb * 64 + m0 + i;
        #pragma unroll
        for (int j = 0; j < 4; j++) {
            int s = sb * 64 + n0 + j;
            out[(size_t)(m0 + i) * TT + n0 + j] =
                (s <= t) ? acc[i][j] * SCALE : -3.402823466e38f;
        }
    }
}

// ---------------- attention row softmax ----------------
__global__ void attn_softmax(float* __restrict__ att) {
    int row = blockIdx.x;
    int t = row & (TT - 1);
    float* p = att + (size_t)row * TT;
    int L = ((t >> 6) + 1) << 6;
    int tid = threadIdx.x;

    float m = -FLT_MAX, s = 0.f;
    for (int i = tid; i < L; i += 256) {
        float x = p[i];
        if (x > m) { s = s * expf(m - x) + 1.f; m = x; }
        else        s += expf(x - m);
    }
    __shared__ float sm[256], ss[256];
    sm[tid] = m; ss[tid] = s; __syncthreads();
    #pragma unroll
    for (int off = 128; off > 0; off >>= 1) {
        if (tid < off) {
            float m2 = sm[tid + off], s2 = ss[tid + off];
            float M = fmaxf(sm[tid], m2);
            ss[tid] = ss[tid] * expf(sm[tid] - M) + s2 * expf(m2 - M);
            sm[tid] = M;
        }
        __syncthreads();
    }
    float gm = sm[0];
    float inv = 1.f / ss[0];
    for (int i = tid; i < L; i += 256)
        p[i] = expf(p[i] - gm) * inv;
}

// ---------------- attention PV (output pre-rounded: feeds Wo GEMM) ----------------
__global__ void attn_pv(const float* __restrict__ att, const float* __restrict__ v,
                        float* __restrict__ o) {
    int tb = blockIdx.x, bh = blockIdx.y;
    int b = bh / NH, h = bh % NH;

    __shared__ float Ps[32][68];
    __shared__ float Vs[32][64];
    int tid = threadIdx.x;
    int tx = tid & 15, ty = tid >> 4;
    int m0 = ty * 4, n0 = tx * 4;

    float acc[4][4];
    #pragma unroll
    for (int i = 0; i < 4; i++)
        #pragma unroll
        for (int j = 0; j < 4; j++) acc[i][j] = 0.f;

    const float* arow = att + ((size_t)bh * TT + (size_t)tb * 64) * TT;
    const float* vb = v + (size_t)b * TT * D + (size_t)h * HD;
    int Smax = (tb + 1) * 64;

    for (int s0 = 0; s0 < Smax; s0 += 32) {
        #pragma unroll
        for (int i = 0; i < 8; i++) {
            int idx = tid + i * 256;
            int m = idx >> 5, kk = idx & 31;
            Ps[kk][m] = arow[(size_t)m * TT + s0 + kk];
        }
        #pragma unroll
        for (int i = 0; i < 8; i++) {
            int idx = tid + i * 256;
            int kk = idx >> 6, n = idx & 63;
            Vs[kk][n] = vb[(size_t)(s0 + kk) * D + n];
        }
        __syncthreads();
        #pragma unroll
        for (int kk = 0; kk < 32; kk++) {
            float a[4], bv[4];
            #pragma unroll
            for (int i = 0; i < 4; i++) a[i]  = Ps[kk][m0 + i];
            #pragma unroll
            for (int j = 0; j < 4; j++) bv[j] = Vs[kk][n0 + j];
            #pragma unroll
            for (int i = 0; i < 4; i++)
                #pragma unroll
                for (int j = 0; j < 4; j++)
                    acc[i][j] = fmaf(a[i], bv[j], acc[i][j]);
        }
        __syncthreads();
    }

    float* ob = o + (size_t)(b * TT + tb * 64) * D + (size_t)h * HD;
    #pragma unroll
    for (int i = 0; i < 4; i++)
        #pragma unroll
        for (int j = 0; j < 4; j++)
            ob[(size_t)(m0 + i) * D + n0 + j] = tf32f(acc[i][j]);
}

// ---------------- per-row NLL over vocab ----------------
__global__ void nll_kernel(const float* __restrict__ logits,
                           const int* __restrict__ targets,
                           float* __restrict__ nll) {
    int row = blockIdx.x;
    const float* lr = logits + (size_t)row * VV;
    int tid = threadIdx.x;

    float m = -FLT_MAX, s = 0.f;
    for (int i = tid; i < VV; i += 256) {
        float x = lr[i];
        if (x > m) { s = s * expf(m - x) + 1.f; m = x; }
        else        s += expf(x - m);
    }
    __shared__ float sm[256], ss[256];
    sm[tid] = m; ss[tid] = s; __syncthreads();
    #pragma unroll
    for (int off = 128; off > 0; off >>= 1) {
        if (tid < off) {
            float m2 = sm[tid + off], s2 = ss[tid + off];
            float M = fmaxf(sm[tid], m2);
            ss[tid] = ss[tid] * expf(sm[tid] - M) + s2 * expf(m2 - M);
            sm[tid] = M;
        }
        __syncthreads();
    }
    if (tid == 0)
        nll[row] = sm[0] + logf(ss[0]) - lr[targets[row]];
}

__global__ void loss_kernel(const float* __restrict__ nll, float* __restrict__ dst,
                            int nextra) {
    __shared__ float red[256];
    int tid = threadIdx.x;
    float s = 0.f;
    for (int i = tid; i < BT; i += 256) s += nll[i];
    red[tid] = s; __syncthreads();
    #pragma unroll
    for (int off = 128; off > 0; off >>= 1) {
        if (tid < off) red[tid] += red[tid + off];
        __syncthreads();
    }
    if (tid == 0) {
        float loss = red[0] * (1.f / BT);
        for (int i = 0; i < nextra; i++) dst[i] = loss;
    }
}

// ---------------- launch ----------------
extern "C" void kernel_launch(void* const* d_in, const int* in_sizes, int n_in,
                              void* d_out, int out_size) {
    const int*   idx     = (const int*)  d_in[0];
    const int*   targets = (const int*)  d_in[1];
    const float* tok_emb = (const float*)d_in[2];
    const float* pos_emb = (const float*)d_in[3];
    const float* Wq      = (const float*)d_in[4];
    const float* Wk      = (const float*)d_in[5];
    const float* Wv      = (const float*)d_in[6];
    const float* Wo      = (const float*)d_in[7];
    const float* bo      = (const float*)d_in[8];
    const float* ln1_g   = (const float*)d_in[9];
    const float* ln1_b   = (const float*)d_in[10];
    const float* ln2_g   = (const float*)d_in[11];
    const float* ln2_b   = (const float*)d_in[12];
    const float* W1      = (const float*)d_in[13];
    const float* b1      = (const float*)d_in[14];
    const float* W2      = (const float*)d_in[15];
    const float* b2      = (const float*)d_in[16];
    const float* Wlm     = (const float*)d_in[17];
    const float* blm     = (const float*)d_in[18];

    float *x, *h, *q, *k, *v, *o, *ff, *att, *nll;
    float *rwq, *rwk, *rwv, *rwo, *rw1, *rw2, *rwlm;
    cudaGetSymbolAddress((void**)&x,   g_x);
    cudaGetSymbolAddress((void**)&h,   g_h);
    cudaGetSymbolAddress((void**)&q,   g_q);
    cudaGetSymbolAddress((void**)&k,   g_k);
    cudaGetSymbolAddress((void**)&v,   g_v);
    cudaGetSymbolAddress((void**)&o,   g_o);
    cudaGetSymbolAddress((void**)&ff,  g_ff);
    cudaGetSymbolAddress((void**)&att, g_att);
    cudaGetSymbolAddress((void**)&nll, g_nll);
    cudaGetSymbolAddress((void**)&rwq, g_rwq);
    cudaGetSymbolAddress((void**)&rwk, g_rwk);
    cudaGetSymbolAddress((void**)&rwv, g_rwv);
    cudaGetSymbolAddress((void**)&rwo, g_rwo);
    cudaGetSymbolAddress((void**)&rw1, g_rw1);
    cudaGetSymbolAddress((void**)&rw2, g_rw2);
    cudaGetSymbolAddress((void**)&rwlm, g_rwlm);

    cudaFuncSetAttribute(gemm_tf32, cudaFuncAttributeMaxDynamicSharedMemorySize, GSMEM);

    // pre-round all weights to tf32 (deterministic, graph-capturable)
    round_kernel<<<1024, 256>>>(Wq, rwq, (long long)NL * D * D);
    round_kernel<<<1024, 256>>>(Wk, rwk, (long long)NL * D * D);
    round_kernel<<<1024, 256>>>(Wv, rwv, (long long)NL * D * D);
    round_kernel<<<1024, 256>>>(Wo, rwo, (long long)NL * D * D);
    round_kernel<<<2048, 256>>>(W1, rw1, (long long)NL * D * FF);
    round_kernel<<<2048, 256>>>(W2, rw2, (long long)NL * FF * D);
    round_kernel<<<2048, 256>>>(Wlm, rwlm, (long long)D * VV);

    embed_kernel<<<(BT * D + 255) / 256, 256>>>(idx, tok_emb, pos_emb, x);

    dim3 gD(BT / 128, D / 64);               // 32 x 12
    dim3 gF(BT / 128, FF / 64);              // 32 x 48
    dim3 gV(BT / 128, (VV + 63) / 64);       // 32 x 786

    for (int l = 0; l < NL; l++) {
        const float* wq = rwq + (size_t)l * D * D;
        const float* wk = rwk + (size_t)l * D * D;
        const float* wv = rwv + (size_t)l * D * D;
        const float* wo = rwo + (size_t)l * D * D;
        const float* w1 = rw1 + (size_t)l * D * FF;
        const float* w2 = rw2 + (size_t)l * FF * D;

        ln_kernel<<<BT, 256>>>(x, ln1_g + (size_t)l * D, ln1_b + (size_t)l * D, h);
        gemm_tf32<<<gD, 128, GSMEM>>>(h, wq, nullptr, nullptr, q, BT, D, D, 0, 0);
        gemm_tf32<<<gD, 128, GSMEM>>>(h, wk, nullptr, nullptr, k, BT, D, D, 0, 0);
        gemm_tf32<<<gD, 128, GSMEM>>>(h, wv, nullptr, nullptr, v, BT, D, D, 0, 0);

        attn_scores<<<dim3(TT / 64, TT / 64, BH), 256>>>(q, k, att);
        attn_softmax<<<BH * TT, 256>>>(att);
        attn_pv<<<dim3(TT / 64, BH), 256>>>(att, v, o);

        gemm_tf32<<<gD, 128, GSMEM>>>(o, wo, bo + (size_t)l * D, x, x, BT, D, D, 0, 0);

        ln_kernel<<<BT, 256>>>(x, ln2_g + (size_t)l * D, ln2_b + (size_t)l * D, h);
        gemm_tf32<<<gF, 128, GSMEM>>>(h, w1, b1 + (size_t)l * FF, nullptr, ff, BT, FF, D, 1, 1);
        gemm_tf32<<<gD, 128, GSMEM>>>(ff, w2, b2 + (size_t)l * D, x, x, BT, D, FF, 0, 0);
    }

    // rounded copy of x for the LM head A operand
    round_kernel<<<1024, 256>>>(x, h, (long long)BT * D);

    float* logits = (float*)d_out;
    gemm_tf32<<<gV, 128, GSMEM>>>(h, rwlm, blm, nullptr, logits, BT, VV, D, 0, 0);

    long long btv = (long long)BT * VV;
    if ((long long)out_size > btv) {
        nll_kernel<<<BT, 256>>>(logits, targets, nll);
        loss_kernel<<<1, 256>>>(nll, logits + btv, (int)((long long)out_size - btv));
    }
}

// round 5
// speedup vs baseline: 3.0615x; 1.0066x over previous
#include <cuda_runtime.h>
#include <cuda_bf16.h>
#include <float.h>
#include <math.h>

// ---------------- problem constants ----------------
#define NL   12
#define D    768
#define NH   12
#define HD   64
#define VV   50257
#define BB   4
#define TT   1024
#define BT   (BB*TT)          // 4096
#define FF   (4*D)            // 3072
#define BH   (BB*NH)          // 48
#define EPSF 1e-5f
#define SCALE 0.125f          // HD^-0.5

// ---------------- scratch (device globals; no runtime alloc) ----------------
__device__ float g_x[BT*D];
__device__ float g_h[BT*D];
__device__ float g_q[BT*D];
__device__ float g_k[BT*D];
__device__ float g_v[BT*D];
__device__ float g_o[BT*D];
__device__ float g_ff[BT*FF];
__device__ float g_att[(size_t)BH*TT*TT];   // 201 MB
__device__ float g_nll[BT];

// ---------------- tf32 / async helpers ----------------
__device__ __forceinline__ unsigned f2tf(float x) {
    unsigned r;
    asm("cvt.rna.tf32.f32 %0, %1;" : "=r"(r) : "f"(x));
    return r;
}
__device__ __forceinline__ float tf32f(float x) { return __uint_as_float(f2tf(x)); }

__device__ __forceinline__ void mma_tf32(float* d, const unsigned* a, const unsigned* b) {
    asm volatile(
        "mma.sync.aligned.m16n8k8.row.col.f32.tf32.tf32.f32 "
        "{%0,%1,%2,%3}, {%4,%5,%6,%7}, {%8,%9}, {%0,%1,%2,%3};"
        : "+f"(d[0]), "+f"(d[1]), "+f"(d[2]), "+f"(d[3])
        : "r"(a[0]), "r"(a[1]), "r"(a[2]), "r"(a[3]), "r"(b[0]), "r"(b[1]));
}
__device__ __forceinline__ void cp16(void* s, const void* g) {
    unsigned sa = (unsigned)__cvta_generic_to_shared(s);
    asm volatile("cp.async.cg.shared.global [%0], [%1], 16;" :: "r"(sa), "l"(g));
}
__device__ __forceinline__ void cp4z(void* s, const void* g, int srcbytes) {
    unsigned sa = (unsigned)__cvta_generic_to_shared(s);
    asm volatile("cp.async.ca.shared.global [%0], [%1], 4, %2;"
                 :: "r"(sa), "l"(g), "r"(srcbytes));
}
#define CP_COMMIT() asm volatile("cp.async.commit_group;")
#define CP_WAIT1()  asm volatile("cp.async.wait_group 1;")

// ---------------- tf32 rounding pass (grid-stride) ----------------
__global__ void round_kernel(const float* __restrict__ in, float* __restrict__ out,
                             long long n) {
    long long i = (long long)blockIdx.x * blockDim.x + threadIdx.x;
    long long stride = (long long)gridDim.x * blockDim.x;
    for (; i < n; i += stride) out[i] = tf32f(in[i]);
}

// ---------------- embedding ----------------
__global__ void embed_kernel(const int* __restrict__ idx,
                             const float* __restrict__ tok,
                             const float* __restrict__ pos,
                             float* __restrict__ x) {
    int i = blockIdx.x * 256 + threadIdx.x;
    if (i >= BT * D) return;
    int row = i / D;
    int d   = i - row * D;
    int t   = row & (TT - 1);
    x[i] = tok[(size_t)idx[row] * D + d] + pos[(size_t)t * D + d];
}

// ---------------- layernorm (output pre-rounded to tf32) ----------------
__global__ void ln_kernel(const float* __restrict__ x,
                          const float* __restrict__ g,
                          const float* __restrict__ b,
                          float* __restrict__ out) {
    int row = blockIdx.x;
    const float* xr = x + (size_t)row * D;
    __shared__ float sx[D];
    __shared__ float red[256];
    int tid = threadIdx.x;

    float s = 0.f;
    for (int i = tid; i < D; i += 256) { float t = xr[i]; sx[i] = t; s += t; }
    red[tid] = s; __syncthreads();
    #pragma unroll
    for (int off = 128; off > 0; off >>= 1) {
        if (tid < off) red[tid] += red[tid + off];
        __syncthreads();
    }
    float mean = red[0] * (1.f / D);
    __syncthreads();

    float s2 = 0.f;
    for (int i = tid; i < D; i += 256) { float t = sx[i] - mean; s2 += t * t; }
    red[tid] = s2; __syncthreads();
    #pragma unroll
    for (int off = 128; off > 0; off >>= 1) {
        if (tid < off) red[tid] += red[tid + off];
        __syncthreads();
    }
    float rstd = rsqrtf(red[0] * (1.f / D) + EPSF);

    float* orow = out + (size_t)row * D;
    for (int i = tid; i < D; i += 256)
        orow[i] = tf32f((sx[i] - mean) * rstd * g[i] + b[i]);
}

// ---------------- TF32 tensor-core GEMM ----------------
// C[M,N] = A[M,K] @ B[K,N] (+bias) (+resid) (relu?) (round output to tf32?)
// A must be pre-rounded to tf32; B is raw fp32 (cvt.rna on fragment load).
// Block tile 128x64x32, 128 threads = 4 warps as 2(M) x 2(N), warp tile 64x32.
// 2-stage cp.async smem pipeline + register double-buffered fragments.
#define AK    36
#define BN2   68
#define ASTG  (128*AK)          // floats per A stage (4608)
#define BSTG  (32*BN2)          // floats per B stage (2176)
#define BOFF  (2*ASTG)
#define GSMEM ((2*ASTG + 2*BSTG) * 4)   // 54272 bytes

__global__ __launch_bounds__(128, 3)
void gemm_tf32(const float* __restrict__ A, const float* __restrict__ Bm,
               const float* __restrict__ bias, const float* __restrict__ resid,
               float* __restrict__ C, int M, int N, int K, int relu, int roundC) {
    extern __shared__ float smem[];

    const int tid  = threadIdx.x;
    const int lane = tid & 31;
    const int wid  = tid >> 5;
    const int warpM = (wid >> 1) * 64;   // 0,64
    const int warpN = (wid & 1) * 32;    // 0,32
    const int gm = blockIdx.x * 128;
    const int gn = blockIdx.y * 64;
    const int lt = lane & 3;
    const int lg = lane >> 2;
    const bool alignedB = ((N & 3) == 0);

    float acc[4][4][4];
    #pragma unroll
    for (int mi = 0; mi < 4; mi++)
        #pragma unroll
        for (int nj = 0; nj < 4; nj++)
            #pragma unroll
            for (int r = 0; r < 4; r++) acc[mi][nj][r] = 0.f;

    const int nch = K >> 5;

    auto load_tiles = [&](int k0, int stage) {
        float* As = smem + stage * ASTG;
        float* Bs = smem + BOFF + stage * BSTG;
        #pragma unroll
        for (int i = 0; i < 8; i++) {
            int c  = tid + i * 128;        // 0..1023
            int m  = c >> 3;
            int k4 = (c & 7) << 2;
            cp16(As + m * AK + k4, A + (size_t)(gm + m) * K + k0 + k4);
        }
        if (alignedB) {
            #pragma unroll
            for (int i = 0; i < 4; i++) {
                int c  = tid + i * 128;    // 0..511
                int kr = c >> 4;
                int n4 = (c & 15) << 2;
                cp16(Bs + kr * BN2 + n4, Bm + (size_t)(k0 + kr) * N + gn + n4);
            }
        } else {
            #pragma unroll
            for (int i = 0; i < 16; i++) {
                int c  = tid + i * 128;    // 0..2047
                int kr = c >> 6;
                int n  = c & 63;
                int col = gn + n;
                cp4z(Bs + kr * BN2 + n, Bm + (size_t)(k0 + kr) * N + col,
                     (col < N) ? 4 : 0);
            }
        }
    };

    load_tiles(0, 0);
    CP_COMMIT();

    unsigned a[2][4][4], b[2][4][2];

    for (int ch = 0; ch < nch; ch++) {
        int stage = ch & 1;
        if (ch + 1 < nch) load_tiles((ch + 1) << 5, stage ^ 1);
        CP_COMMIT();
        CP_WAIT1();
        __syncthreads();

        const float* Asb = smem + stage * ASTG;
        const float* Bsb = smem + BOFF + stage * BSTG;

        // fragment loader: A raw bits (pre-rounded), B cvt.rna here
        auto load_frag = [&](int kk, int buf) {
            #pragma unroll
            for (int mi = 0; mi < 4; mi++) {
                const float* p0 = Asb + (warpM + mi * 16 + lg) * AK + kk;
                const float* p1 = p0 + 8 * AK;
                a[buf][mi][0] = __float_as_uint(p0[lt]);
                a[buf][mi][1] = __float_as_uint(p1[lt]);
                a[buf][mi][2] = __float_as_uint(p0[lt + 4]);
                a[buf][mi][3] = __float_as_uint(p1[lt + 4]);
            }
            #pragma unroll
            for (int nj = 0; nj < 4; nj++) {
                int nc = warpN + nj * 8 + lg;
                b[buf][nj][0] = f2tf(Bsb[(kk + lt) * BN2 + nc]);
                b[buf][nj][1] = f2tf(Bsb[(kk + lt + 4) * BN2 + nc]);
            }
        };

        load_frag(0, 0);
        #pragma unroll
        for (int kks = 0; kks < 4; kks++) {
            int cur = kks & 1;
            if (kks < 3) load_frag((kks + 1) << 3, cur ^ 1);
            #pragma unroll
            for (int mi = 0; mi < 4; mi++)
                #pragma unroll
                for (int nj = 0; nj < 4; nj++)
                    mma_tf32(acc[mi][nj], a[cur][mi], b[cur][nj]);
        }
        __syncthreads();
    }

    // ---- epilogue ----
    #pragma unroll
    for (int mi = 0; mi < 4; mi++) {
        int r0 = gm + warpM + mi * 16 + lg;
        #pragma unroll
        for (int nj = 0; nj < 4; nj++) {
            int c0 = gn + warpN + nj * 8 + (lt << 1);
            #pragma unroll
            for (int r = 0; r < 4; r++) {
                int rowg = r0 + ((r >> 1) << 3);
                int colg = c0 + (r & 1);
                if (colg < N) {
                    float v = acc[mi][nj][r];
                    if (bias)   v += bias[colg];
                    if (resid)  v += resid[(size_t)rowg * N + colg];
                    if (relu)   v = fmaxf(v, 0.f);
                    if (roundC) v = tf32f(v);
                    C[(size_t)rowg * N + colg] = v;
                }
            }
        }
    }
}

// ---------------- attention: scores = scale * Q K^T with causal mask ----------------
__global__ void attn_scores(const float* __restrict__ q, const float* __restrict__ k,
                            float* __restrict__ att) {
    int tb = blockIdx.x, sb = blockIdx.y, bh = blockIdx.z;
    if (sb > tb) return;
    int b = bh / NH, h = bh % NH;

    __shared__ float Qs[64][65];
    __shared__ float Ks[64][65];
    int tid = threadIdx.x;

    const float* qb = q + (size_t)b * TT * D + (size_t)h * HD;
    const float* kb = k + (size_t)b * TT * D + (size_t)h * HD;
    #pragma unroll
    for (int i = 0; i < 16; i++) {
        int idx = tid + i * 256;
        int m = idx >> 6, d = idx & 63;
        Qs[d][m] = qb[(size_t)(tb * 64 + m) * D + d];
        Ks[d][m] = kb[(size_t)(sb * 64 + m) * D + d];
    }
    __syncthreads();

    int tx = tid & 15, ty = tid >> 4;
    int m0 = ty * 4, n0 = tx * 4;
    float acc[4][4];
    #pragma unroll
    for (int i = 0; i < 4; i++)
        #pragma unroll
        for (int j = 0; j < 4; j++) acc[i][j] = 0.f;

    #pragma unroll
    for (int d = 0; d < 64; d++) {
        float a[4], bv[4];
        #pragma unroll
        for (int i = 0; i < 4; i++) a[i]  = Qs[d][m0 + i];
        #pragma unroll
        for (int j = 0; j < 4; j++) bv[j] = Ks[d][n0 + j];
        #pragma unroll
        for (int i = 0; i < 4; i++)
            #pragma unroll
            for (int j = 0; j < 4; j++)
                acc[i][j] = fmaf(a[i], bv[j], acc[i][j]);
    }

    float* out = att + ((size_t)bh * TT + (size_t)tb * 64) * TT + (size_t)sb * 64;
    #pragma unroll
    for (int i = 0; i < 4; i++) {
        int t = tb * 64 + m0 + i;
        #pragma unroll
        for (int j = 0; j < 4; j++) {
            int s = sb * 64 + n0 + j;
            out[(size_t)(m0 + i) * TT + n0 + j] =
                (s <= t) ? acc[i][j] * SCALE : -3.402823466e38f;
        }
    }
}

// ---------------- attention row softmax ----------------
__global__ void attn_softmax(float* __restrict__ att) {
    int row = blockIdx.x;
    int t = row & (TT - 1);
    float* p = att + (size_t)row * TT;
    int L = ((t >> 6) + 1) << 6;
    int tid = threadIdx.x;

    float m = -FLT_MAX, s = 0.f;
    for (int i = tid; i < L; i += 256) {
        float x = p[i];
        if (x > m) { s = s * expf(m - x) + 1.f; m = x; }
        else        s += expf(x - m);
    }
    __shared__ float sm[256], ss[256];
    sm[tid] = m; ss[tid] = s; __syncthreads();
    #pragma unroll
    for (int off = 128; off > 0; off >>= 1) {
        if (tid < off) {
            float m2 = sm[tid + off], s2 = ss[tid + off];
            float M = fmaxf(sm[tid], m2);
            ss[tid] = ss[tid] * expf(sm[tid] - M) + s2 * expf(m2 - M);
            sm[tid] = M;
        }
        __syncthreads();
    }
    float gm = sm[0];
    float inv = 1.f / ss[0];
    for (int i = tid; i < L; i += 256)
        p[i] = expf(p[i] - gm) * inv;
}

// ---------------- attention PV (output pre-rounded: feeds Wo GEMM) ----------------
__global__ void attn_pv(const float* __restrict__ att, const float* __restrict__ v,
                        float* __restrict__ o) {
    int tb = blockIdx.x, bh = blockIdx.y;
    int b = bh / NH, h = bh % NH;

    __shared__ float Ps[32][68];
    __shared__ float Vs[32][64];
    int tid = threadIdx.x;
    int tx = tid & 15, ty = tid >> 4;
    int m0 = ty * 4, n0 = tx * 4;

    float acc[4][4];
    #pragma unroll
    for (int i = 0; i < 4; i++)
        #pragma unroll
        for (int j = 0; j < 4; j++) acc[i][j] = 0.f;

    const float* arow = att + ((size_t)bh * TT + (size_t)tb * 64) * TT;
    const float* vb = v + (size_t)b * TT * D + (size_t)h * HD;
    int Smax = (tb + 1) * 64;

    for (int s0 = 0; s0 < Smax; s0 += 32) {
        #pragma unroll
        for (int i = 0; i < 8; i++) {
            int idx = tid + i * 256;
            int m = idx >> 5, kk = idx & 31;
            Ps[kk][m] = arow[(size_t)m * TT + s0 + kk];
        }
        #pragma unroll
        for (int i = 0; i < 8; i++) {
            int idx = tid + i * 256;
            int kk = idx >> 6, n = idx & 63;
            Vs[kk][n] = vb[(size_t)(s0 + kk) * D + n];
        }
        __syncthreads();
        #pragma unroll
        for (int kk = 0; kk < 32; kk++) {
            float a[4], bv[4];
            #pragma unroll
            for (int i = 0; i < 4; i++) a[i]  = Ps[kk][m0 + i];
            #pragma unroll
            for (int j = 0; j < 4; j++) bv[j] = Vs[kk][n0 + j];
            #pragma unroll
            for (int i = 0; i < 4; i++)
                #pragma unroll
                for (int j = 0; j < 4; j++)
                    acc[i][j] = fmaf(a[i], bv[j], acc[i][j]);
        }
        __syncthreads();
    }

    float* ob = o + (size_t)(b * TT + tb * 64) * D + (size_t)h * HD;
    #pragma unroll
    for (int i = 0; i < 4; i++)
        #pragma unroll
        for (int j = 0; j < 4; j++)
            ob[(size_t)(m0 + i) * D + n0 + j] = tf32f(acc[i][j]);
}

// ---------------- per-row NLL over vocab ----------------
__global__ void nll_kernel(const float* __restrict__ logits,
                           const int* __restrict__ targets,
                           float* __restrict__ nll) {
    int row = blockIdx.x;
    const float* lr = logits + (size_t)row * VV;
    int tid = threadIdx.x;

    float m = -FLT_MAX, s = 0.f;
    for (int i = tid; i < VV; i += 256) {
        float x = lr[i];
        if (x > m) { s = s * expf(m - x) + 1.f; m = x; }
        else        s += expf(x - m);
    }
    __shared__ float sm[256], ss[256];
    sm[tid] = m; ss[tid] = s; __syncthreads();
    #pragma unroll
    for (int off = 128; off > 0; off >>= 1) {
        if (tid < off) {
            float m2 = sm[tid + off], s2 = ss[tid + off];
            float M = fmaxf(sm[tid], m2);
            ss[tid] = ss[tid] * expf(sm[tid] - M) + s2 * expf(m2 - M);
            sm[tid] = M;
        }
        __syncthreads();
    }
    if (tid == 0)
        nll[row] = sm[0] + logf(ss[0]) - lr[targets[row]];
}

__global__ void loss_kernel(const float* __restrict__ nll, float* __restrict__ dst,
                            int nextra) {
    __shared__ float red[256];
    int tid = threadIdx.x;
    float s = 0.f;
    for (int i = tid; i < BT; i += 256) s += nll[i];
    red[tid] = s; __syncthreads();
    #pragma unroll
    for (int off = 128; off > 0; off >>= 1) {
        if (tid < off) red[tid] += red[tid + off];
        __syncthreads();
    }
    if (tid == 0) {
        float loss = red[0] * (1.f / BT);
        for (int i = 0; i < nextra; i++) dst[i] = loss;
    }
}

// ---------------- launch ----------------
extern "C" void kernel_launch(void* const* d_in, const int* in_sizes, int n_in,
                              void* d_out, int out_size) {
    const int*   idx     = (const int*)  d_in[0];
    const int*   targets = (const int*)  d_in[1];
    const float* tok_emb = (const float*)d_in[2];
    const float* pos_emb = (const float*)d_in[3];
    const float* Wq      = (const float*)d_in[4];
    const float* Wk      = (const float*)d_in[5];
    const float* Wv      = (const float*)d_in[6];
    const float* Wo      = (const float*)d_in[7];
    const float* bo      = (const float*)d_in[8];
    const float* ln1_g   = (const float*)d_in[9];
    const float* ln1_b   = (const float*)d_in[10];
    const float* ln2_g   = (const float*)d_in[11];
    const float* ln2_b   = (const float*)d_in[12];
    const float* W1      = (const float*)d_in[13];
    const float* b1      = (const float*)d_in[14];
    const float* W2      = (const float*)d_in[15];
    const float* b2      = (const float*)d_in[16];
    const float* Wlm     = (const float*)d_in[17];
    const float* blm     = (const float*)d_in[18];

    float *x, *h, *q, *k, *v, *o, *ff, *att, *nll;
    cudaGetSymbolAddress((void**)&x,   g_x);
    cudaGetSymbolAddress((void**)&h,   g_h);
    cudaGetSymbolAddress((void**)&q,   g_q);
    cudaGetSymbolAddress((void**)&k,   g_k);
    cudaGetSymbolAddress((void**)&v,   g_v);
    cudaGetSymbolAddress((void**)&o,   g_o);
    cudaGetSymbolAddress((void**)&ff,  g_ff);
    cudaGetSymbolAddress((void**)&att, g_att);
    cudaGetSymbolAddress((void**)&nll, g_nll);

    cudaFuncSetAttribute(gemm_tf32, cudaFuncAttributeMaxDynamicSharedMemorySize, GSMEM);

    embed_kernel<<<(BT * D + 255) / 256, 256>>>(idx, tok_emb, pos_emb, x);

    dim3 gD(BT / 128, D / 64);               // 32 x 12
    dim3 gF(BT / 128, FF / 64);              // 32 x 48
    dim3 gV(BT / 128, (VV + 63) / 64);       // 32 x 786

    for (int l = 0; l < NL; l++) {
        const float* wq = Wq + (size_t)l * D * D;
        const float* wk = Wk + (size_t)l * D * D;
        const float* wv = Wv + (size_t)l * D * D;
        const float* wo = Wo + (size_t)l * D * D;
        const float* w1 = W1 + (size_t)l * D * FF;
        const float* w2 = W2 + (size_t)l * FF * D;

        ln_kernel<<<BT, 256>>>(x, ln1_g + (size_t)l * D, ln1_b + (size_t)l * D, h);
        gemm_tf32<<<gD, 128, GSMEM>>>(h, wq, nullptr, nullptr, q, BT, D, D, 0, 0);
        gemm_tf32<<<gD, 128, GSMEM>>>(h, wk, nullptr, nullptr, k, BT, D, D, 0, 0);
        gemm_tf32<<<gD, 128, GSMEM>>>(h, wv, nullptr, nullptr, v, BT, D, D, 0, 0);

        attn_scores<<<dim3(TT / 64, TT / 64, BH), 256>>>(q, k, att);
        attn_softmax<<<BH * TT, 256>>>(att);
        attn_pv<<<dim3(TT / 64, BH), 256>>>(att, v, o);

        gemm_tf32<<<gD, 128, GSMEM>>>(o, wo, bo + (size_t)l * D, x, x, BT, D, D, 0, 0);

        ln_kernel<<<BT, 256>>>(x, ln2_g + (size_t)l * D, ln2_b + (size_t)l * D, h);
        gemm_tf32<<<gF, 128, GSMEM>>>(h, w1, b1 + (size_t)l * FF, nullptr, ff, BT, FF, D, 1, 1);
        gemm_tf32<<<gD, 128, GSMEM>>>(ff, w2, b2 + (size_t)l * D, x, x, BT, D, FF, 0, 0);
    }

    // rounded copy of x for the LM head A operand
    round_kernel<<<1024, 256>>>(x, h, (long long)BT * D);

    float* logits = (float*)d_out;
    gemm_tf32<<<gV, 128, GSMEM>>>(h, Wlm, blm, nullptr, logits, BT, VV, D, 0, 0);

    long long btv = (long long)BT * VV;
    if ((long long)out_size > btv) {
        nll_kernel<<<BT, 256>>>(logits, targets, nll);
        loss_kernel<<<1, 256>>>(nll, logits + btv, (int)((long long)out_size - btv));
    }
}

// round 6
// speedup vs baseline: 3.3671x; 1.0998x over previous
#include <cuda_runtime.h>
#include <cuda_bf16.h>
#include <float.h>
#include <math.h>

// ---------------- problem constants ----------------
#define NL   12
#define D    768
#define NH   12
#define HD   64
#define VV   50257
#define BB   4
#define TT   1024
#define BT   (BB*TT)          // 4096
#define FF   (4*D)            // 3072
#define BH   (BB*NH)          // 48
#define EPSF 1e-5f
#define SCALE 0.125f          // HD^-0.5

// ---------------- scratch (device globals; no runtime alloc) ----------------
__device__ float g_x[BT*D];
__device__ float g_h[BT*D];
__device__ float g_q[BT*D];
__device__ float g_k[BT*D];
__device__ float g_v[BT*D];
__device__ float g_o[BT*D];
__device__ float g_ff[BT*FF];
__device__ float g_att[(size_t)BH*TT*TT];   // 201 MB
__device__ float g_nll[BT];

// ---------------- tf32 / async helpers ----------------
__device__ __forceinline__ unsigned f2tf(float x) {
    unsigned r;
    asm("cvt.rna.tf32.f32 %0, %1;" : "=r"(r) : "f"(x));
    return r;
}
__device__ __forceinline__ float tf32f(float x) { return __uint_as_float(f2tf(x)); }

__device__ __forceinline__ void mma_tf32(float* d, const unsigned* a, const unsigned* b) {
    asm volatile(
        "mma.sync.aligned.m16n8k8.row.col.f32.tf32.tf32.f32 "
        "{%0,%1,%2,%3}, {%4,%5,%6,%7}, {%8,%9}, {%0,%1,%2,%3};"
        : "+f"(d[0]), "+f"(d[1]), "+f"(d[2]), "+f"(d[3])
        : "r"(a[0]), "r"(a[1]), "r"(a[2]), "r"(a[3]), "r"(b[0]), "r"(b[1]));
}
__device__ __forceinline__ void cp16(void* s, const void* g) {
    unsigned sa = (unsigned)__cvta_generic_to_shared(s);
    asm volatile("cp.async.cg.shared.global [%0], [%1], 16;" :: "r"(sa), "l"(g));
}
__device__ __forceinline__ void cp4z(void* s, const void* g, int srcbytes) {
    unsigned sa = (unsigned)__cvta_generic_to_shared(s);
    asm volatile("cp.async.ca.shared.global [%0], [%1], 4, %2;"
                 :: "r"(sa), "l"(g), "r"(srcbytes));
}
#define CP_COMMIT() asm volatile("cp.async.commit_group;")
#define CP_WAIT1()  asm volatile("cp.async.wait_group 1;")

// ---------------- tf32 rounding pass (grid-stride) ----------------
__global__ void round_kernel(const float* __restrict__ in, float* __restrict__ out,
                             long long n) {
    long long i = (long long)blockIdx.x * blockDim.x + threadIdx.x;
    long long stride = (long long)gridDim.x * blockDim.x;
    for (; i < n; i += stride) out[i] = tf32f(in[i]);
}

// ---------------- embedding ----------------
__global__ void embed_kernel(const int* __restrict__ idx,
                             const float* __restrict__ tok,
                             const float* __restrict__ pos,
                             float* __restrict__ x) {
    int i = blockIdx.x * 256 + threadIdx.x;
    if (i >= BT * D) return;
    int row = i / D;
    int d   = i - row * D;
    int t   = row & (TT - 1);
    x[i] = tok[(size_t)idx[row] * D + d] + pos[(size_t)t * D + d];
}

// ---------------- layernorm (output pre-rounded to tf32) ----------------
__global__ void ln_kernel(const float* __restrict__ x,
                          const float* __restrict__ g,
                          const float* __restrict__ b,
                          float* __restrict__ out) {
    int row = blockIdx.x;
    const float* xr = x + (size_t)row * D;
    __shared__ float sx[D];
    __shared__ float red[256];
    int tid = threadIdx.x;

    float s = 0.f;
    for (int i = tid; i < D; i += 256) { float t = xr[i]; sx[i] = t; s += t; }
    red[tid] = s; __syncthreads();
    #pragma unroll
    for (int off = 128; off > 0; off >>= 1) {
        if (tid < off) red[tid] += red[tid + off];
        __syncthreads();
    }
    float mean = red[0] * (1.f / D);
    __syncthreads();

    float s2 = 0.f;
    for (int i = tid; i < D; i += 256) { float t = sx[i] - mean; s2 += t * t; }
    red[tid] = s2; __syncthreads();
    #pragma unroll
    for (int off = 128; off > 0; off >>= 1) {
        if (tid < off) red[tid] += red[tid + off];
        __syncthreads();
    }
    float rstd = rsqrtf(red[0] * (1.f / D) + EPSF);

    float* orow = out + (size_t)row * D;
    for (int i = tid; i < D; i += 256)
        orow[i] = tf32f((sx[i] - mean) * rstd * g[i] + b[i]);
}

// ---------------- TF32 tensor-core GEMM (unchanged from R5) ----------------
#define AK    36
#define BN2   68
#define ASTG  (128*AK)
#define BSTG  (32*BN2)
#define BOFF  (2*ASTG)
#define GSMEM ((2*ASTG + 2*BSTG) * 4)   // 54272 bytes

__global__ __launch_bounds__(128, 3)
void gemm_tf32(const float* __restrict__ A, const float* __restrict__ Bm,
               const float* __restrict__ bias, const float* __restrict__ resid,
               float* __restrict__ C, int M, int N, int K, int relu, int roundC) {
    extern __shared__ float smem[];

    const int tid  = threadIdx.x;
    const int lane = tid & 31;
    const int wid  = tid >> 5;
    const int warpM = (wid >> 1) * 64;
    const int warpN = (wid & 1) * 32;
    const int gm = blockIdx.x * 128;
    const int gn = blockIdx.y * 64;
    const int lt = lane & 3;
    const int lg = lane >> 2;
    const bool alignedB = ((N & 3) == 0);

    float acc[4][4][4];
    #pragma unroll
    for (int mi = 0; mi < 4; mi++)
        #pragma unroll
        for (int nj = 0; nj < 4; nj++)
            #pragma unroll
            for (int r = 0; r < 4; r++) acc[mi][nj][r] = 0.f;

    const int nch = K >> 5;

    auto load_tiles = [&](int k0, int stage) {
        float* As = smem + stage * ASTG;
        float* Bs = smem + BOFF + stage * BSTG;
        #pragma unroll
        for (int i = 0; i < 8; i++) {
            int c  = tid + i * 128;
            int m  = c >> 3;
            int k4 = (c & 7) << 2;
            cp16(As + m * AK + k4, A + (size_t)(gm + m) * K + k0 + k4);
        }
        if (alignedB) {
            #pragma unroll
            for (int i = 0; i < 4; i++) {
                int c  = tid + i * 128;
                int kr = c >> 4;
                int n4 = (c & 15) << 2;
                cp16(Bs + kr * BN2 + n4, Bm + (size_t)(k0 + kr) * N + gn + n4);
            }
        } else {
            #pragma unroll
            for (int i = 0; i < 16; i++) {
                int c  = tid + i * 128;
                int kr = c >> 6;
                int n  = c & 63;
                int col = gn + n;
                cp4z(Bs + kr * BN2 + n, Bm + (size_t)(k0 + kr) * N + col,
                     (col < N) ? 4 : 0);
            }
        }
    };

    load_tiles(0, 0);
    CP_COMMIT();

    unsigned a[2][4][4], b[2][4][2];

    for (int ch = 0; ch < nch; ch++) {
        int stage = ch & 1;
        if (ch + 1 < nch) load_tiles((ch + 1) << 5, stage ^ 1);
        CP_COMMIT();
        CP_WAIT1();
        __syncthreads();

        const float* Asb = smem + stage * ASTG;
        const float* Bsb = smem + BOFF + stage * BSTG;

        auto load_frag = [&](int kk, int buf) {
            #pragma unroll
            for (int mi = 0; mi < 4; mi++) {
                const float* p0 = Asb + (warpM + mi * 16 + lg) * AK + kk;
                const float* p1 = p0 + 8 * AK;
                a[buf][mi][0] = __float_as_uint(p0[lt]);
                a[buf][mi][1] = __float_as_uint(p1[lt]);
                a[buf][mi][2] = __float_as_uint(p0[lt + 4]);
                a[buf][mi][3] = __float_as_uint(p1[lt + 4]);
            }
            #pragma unroll
            for (int nj = 0; nj < 4; nj++) {
                int nc = warpN + nj * 8 + lg;
                b[buf][nj][0] = f2tf(Bsb[(kk + lt) * BN2 + nc]);
                b[buf][nj][1] = f2tf(Bsb[(kk + lt + 4) * BN2 + nc]);
            }
        };

        load_frag(0, 0);
        #pragma unroll
        for (int kks = 0; kks < 4; kks++) {
            int cur = kks & 1;
            if (kks < 3) load_frag((kks + 1) << 3, cur ^ 1);
            #pragma unroll
            for (int mi = 0; mi < 4; mi++)
                #pragma unroll
                for (int nj = 0; nj < 4; nj++)
                    mma_tf32(acc[mi][nj], a[cur][mi], b[cur][nj]);
        }
        __syncthreads();
    }

    #pragma unroll
    for (int mi = 0; mi < 4; mi++) {
        int r0 = gm + warpM + mi * 16 + lg;
        #pragma unroll
        for (int nj = 0; nj < 4; nj++) {
            int c0 = gn + warpN + nj * 8 + (lt << 1);
            #pragma unroll
            for (int r = 0; r < 4; r++) {
                int rowg = r0 + ((r >> 1) << 3);
                int colg = c0 + (r & 1);
                if (colg < N) {
                    float v = acc[mi][nj][r];
                    if (bias)   v += bias[colg];
                    if (resid)  v += resid[(size_t)rowg * N + colg];
                    if (relu)   v = fmaxf(v, 0.f);
                    if (roundC) v = tf32f(v);
                    C[(size_t)rowg * N + colg] = v;
                }
            }
        }
    }
}

// ---------------- attention scores via tf32 mma: scale * Q K^T + causal ----------------
// Block: 128 threads = 4 warps as 2(M)x2(N), warp tile 32x32, tile 64x64, K=HD=64.
#define QP 68
#define KP 65
__global__ __launch_bounds__(128)
void attn_scores(const float* __restrict__ q, const float* __restrict__ k,
                 float* __restrict__ att) {
    int tb = blockIdx.x, sb = blockIdx.y, bh = blockIdx.z;
    if (sb > tb) return;
    int b = bh / NH, h = bh % NH;

    __shared__ float Qs[64 * QP];   // [m][d]
    __shared__ float Ks[64 * KP];   // [d][s]
    const int tid  = threadIdx.x;
    const int lane = tid & 31;
    const int wid  = tid >> 5;
    const int warpM = (wid >> 1) * 32;
    const int warpN = (wid & 1) * 32;
    const int lt = lane & 3;
    const int lg = lane >> 2;

    const float* qb = q + (size_t)b * TT * D + (size_t)h * HD;
    const float* kb = k + (size_t)b * TT * D + (size_t)h * HD;

    // Q tile: 64 rows x 64 d, vectorized
    #pragma unroll
    for (int i = 0; i < 8; i++) {
        int c  = tid + i * 128;          // 0..1023 float4 slots
        int m  = c >> 4;
        int d4 = (c & 15) << 2;
        *(float4*)(Qs + m * QP + d4) =
            *(const float4*)(qb + (size_t)(tb * 64 + m) * D + d4);
    }
    // K tile transposed: Ks[d][s], d-fast enumeration (coalesced global, conflict-free store)
    #pragma unroll
    for (int i = 0; i < 32; i++) {
        int c = tid + i * 128;           // 0..4095
        int s = c >> 6;
        int d = c & 63;
        Ks[d * KP + s] = kb[(size_t)(sb * 64 + s) * D + d];
    }
    __syncthreads();

    float acc[2][4][4];
    #pragma unroll
    for (int mi = 0; mi < 2; mi++)
        #pragma unroll
        for (int nj = 0; nj < 4; nj++)
            #pragma unroll
            for (int r = 0; r < 4; r++) acc[mi][nj][r] = 0.f;

    #pragma unroll
    for (int kk = 0; kk < 64; kk += 8) {
        unsigned a[2][4], bfr[4][2];
        #pragma unroll
        for (int mi = 0; mi < 2; mi++) {
            const float* p0 = Qs + (warpM + mi * 16 + lg) * QP + kk;
            const float* p1 = p0 + 8 * QP;
            a[mi][0] = f2tf(p0[lt]);
            a[mi][1] = f2tf(p1[lt]);
            a[mi][2] = f2tf(p0[lt + 4]);
            a[mi][3] = f2tf(p1[lt + 4]);
        }
        #pragma unroll
        for (int nj = 0; nj < 4; nj++) {
            int nc = warpN + nj * 8 + lg;
            bfr[nj][0] = f2tf(Ks[(kk + lt) * KP + nc]);
            bfr[nj][1] = f2tf(Ks[(kk + lt + 4) * KP + nc]);
        }
        #pragma unroll
        for (int mi = 0; mi < 2; mi++)
            #pragma unroll
            for (int nj = 0; nj < 4; nj++)
                mma_tf32(acc[mi][nj], a[mi], bfr[nj]);
    }

    float* out = att + ((size_t)bh * TT + (size_t)tb * 64) * TT + (size_t)sb * 64;
    #pragma unroll
    for (int mi = 0; mi < 2; mi++) {
        int tl0 = warpM + mi * 16 + lg;
        #pragma unroll
        for (int nj = 0; nj < 4; nj++) {
            int sl0 = warpN + nj * 8 + (lt << 1);
            #pragma unroll
            for (int r = 0; r < 4; r++) {
                int tl = tl0 + ((r >> 1) << 3);
                int sl = sl0 + (r & 1);
                int tg = tb * 64 + tl;
                int sg = sb * 64 + sl;
                out[(size_t)tl * TT + sl] =
                    (sg <= tg) ? acc[mi][nj][r] * SCALE : -3.402823466e38f;
            }
        }
    }
}

// ---------------- attention row softmax (fast exp) ----------------
__global__ void attn_softmax(float* __restrict__ att) {
    int row = blockIdx.x;
    int t = row & (TT - 1);
    float* p = att + (size_t)row * TT;
    int L = ((t >> 6) + 1) << 6;
    int tid = threadIdx.x;

    float m = -FLT_MAX;
    for (int i = tid; i < L; i += 256) m = fmaxf(m, p[i]);
    __shared__ float sm[256], ss[256];
    sm[tid] = m; __syncthreads();
    #pragma unroll
    for (int off = 128; off > 0; off >>= 1) {
        if (tid < off) sm[tid] = fmaxf(sm[tid], sm[tid + off]);
        __syncthreads();
    }
    float gm = sm[0];

    float s = 0.f;
    for (int i = tid; i < L; i += 256) s += __expf(p[i] - gm);
    ss[tid] = s; __syncthreads();
    #pragma unroll
    for (int off = 128; off > 0; off >>= 1) {
        if (tid < off) ss[tid] += ss[tid + off];
        __syncthreads();
    }
    float inv = 1.f / ss[0];
    for (int i = tid; i < L; i += 256)
        p[i] = __expf(p[i] - gm) * inv;
}

// ---------------- attention PV via tf32 mma: O = P @ V ----------------
// Block: 128 threads = 4 warps as 2(M)x2(N), warp tile 32x32, tile 64x64(HD), K chunks of 64.
#define PP 68
#define VP 68
__global__ __launch_bounds__(128)
void attn_pv(const float* __restrict__ att, const float* __restrict__ v,
             float* __restrict__ o) {
    int tb = blockIdx.x, bh = blockIdx.y;
    int b = bh / NH, h = bh % NH;

    __shared__ float Ps[64 * PP];   // [t][s]
    __shared__ float Vs[64 * VP];   // [s][d]
    const int tid  = threadIdx.x;
    const int lane = tid & 31;
    const int wid  = tid >> 5;
    const int warpM = (wid >> 1) * 32;
    const int warpN = (wid & 1) * 32;
    const int lt = lane & 3;
    const int lg = lane >> 2;

    const float* arow = att + ((size_t)bh * TT + (size_t)tb * 64) * TT;
    const float* vb = v + (size_t)b * TT * D + (size_t)h * HD;
    int Smax = (tb + 1) * 64;

    float acc[2][4][4];
    #pragma unroll
    for (int mi = 0; mi < 2; mi++)
        #pragma unroll
        for (int nj = 0; nj < 4; nj++)
            #pragma unroll
            for (int r = 0; r < 4; r++) acc[mi][nj][r] = 0.f;

    for (int s0 = 0; s0 < Smax; s0 += 64) {
        #pragma unroll
        for (int i = 0; i < 8; i++) {
            int c  = tid + i * 128;
            int m  = c >> 4;
            int s4 = (c & 15) << 2;
            *(float4*)(Ps + m * PP + s4) =
                *(const float4*)(arow + (size_t)m * TT + s0 + s4);
            *(float4*)(Vs + m * VP + s4) =
                *(const float4*)(vb + (size_t)(s0 + m) * D + s4);
        }
        __syncthreads();

        #pragma unroll
        for (int kk = 0; kk < 64; kk += 8) {
            unsigned a[2][4], bfr[4][2];
            #pragma unroll
            for (int mi = 0; mi < 2; mi++) {
                const float* p0 = Ps + (warpM + mi * 16 + lg) * PP + kk;
                const float* p1 = p0 + 8 * PP;
                a[mi][0] = f2tf(p0[lt]);
                a[mi][1] = f2tf(p1[lt]);
                a[mi][2] = f2tf(p0[lt + 4]);
                a[mi][3] = f2tf(p1[lt + 4]);
            }
            #pragma unroll
            for (int nj = 0; nj < 4; nj++) {
                int nc = warpN + nj * 8 + lg;
                bfr[nj][0] = f2tf(Vs[(kk + lt) * VP + nc]);
                bfr[nj][1] = f2tf(Vs[(kk + lt + 4) * VP + nc]);
            }
            #pragma unroll
            for (int mi = 0; mi < 2; mi++)
                #pragma unroll
                for (int nj = 0; nj < 4; nj++)
                    mma_tf32(acc[mi][nj], a[mi], bfr[nj]);
        }
        __syncthreads();
    }

    float* ob = o + (size_t)(b * TT + tb * 64) * D + (size_t)h * HD;
    #pragma unroll
    for (int mi = 0; mi < 2; mi++) {
        int tl0 = warpM + mi * 16 + lg;
        #pragma unroll
        for (int nj = 0; nj < 4; nj++) {
            int dl0 = warpN + nj * 8 + (lt << 1);
            #pragma unroll
            for (int r = 0; r < 4; r++) {
                int tl = tl0 + ((r >> 1) << 3);
                int dl = dl0 + (r & 1);
                ob[(size_t)tl * D + dl] = tf32f(acc[mi][nj][r]);
            }
        }
    }
}

// ---------------- per-row NLL over vocab (fast exp, 2 passes, row L2-hot) ----------------
__global__ void nll_kernel(const float* __restrict__ logits,
                           const int* __restrict__ targets,
                           float* __restrict__ nll) {
    int row = blockIdx.x;
    const float* lr = logits + (size_t)row * VV;
    int tid = threadIdx.x;
    __shared__ float red[256];

    float m = -FLT_MAX;
    for (int i = tid; i < VV; i += 256) m = fmaxf(m, lr[i]);
    red[tid] = m; __syncthreads();
    #pragma unroll
    for (int off = 128; off > 0; off >>= 1) {
        if (tid < off) red[tid] = fmaxf(red[tid], red[tid + off]);
        __syncthreads();
    }
    float gm = red[0];
    __syncthreads();

    float s0 = 0.f, s1 = 0.f, s2 = 0.f, s3 = 0.f;
    int i = tid;
    for (; i + 768 < VV; i += 1024) {
        s0 += __expf(lr[i]       - gm);
        s1 += __expf(lr[i + 256] - gm);
        s2 += __expf(lr[i + 512] - gm);
        s3 += __expf(lr[i + 768] - gm);
    }
    for (; i < VV; i += 256) s0 += __expf(lr[i] - gm);
    red[tid] = (s0 + s1) + (s2 + s3); __syncthreads();
    #pragma unroll
    for (int off = 128; off > 0; off >>= 1) {
        if (tid < off) red[tid] += red[tid + off];
        __syncthreads();
    }
    if (tid == 0)
        nll[row] = gm + logf(red[0]) - lr[targets[row]];
}

__global__ void loss_kernel(const float* __restrict__ nll, float* __restrict__ dst,
                            int nextra) {
    __shared__ float red[256];
    int tid = threadIdx.x;
    float s = 0.f;
    for (int i = tid; i < BT; i += 256) s += nll[i];
    red[tid] = s; __syncthreads();
    #pragma unroll
    for (int off = 128; off > 0; off >>= 1) {
        if (tid < off) red[tid] += red[tid + off];
        __syncthreads();
    }
    if (tid == 0) {
        float loss = red[0] * (1.f / BT);
        for (int i = 0; i < nextra; i++) dst[i] = loss;
    }
}

// ---------------- launch ----------------
extern "C" void kernel_launch(void* const* d_in, const int* in_sizes, int n_in,
                              void* d_out, int out_size) {
    const int*   idx     = (const int*)  d_in[0];
    const int*   targets = (const int*)  d_in[1];
    const float* tok_emb = (const float*)d_in[2];
    const float* pos_emb = (const float*)d_in[3];
    const float* Wq      = (const float*)d_in[4];
    const float* Wk      = (const float*)d_in[5];
    const float* Wv      = (const float*)d_in[6];
    const float* Wo      = (const float*)d_in[7];
    const float* bo      = (const float*)d_in[8];
    const float* ln1_g   = (const float*)d_in[9];
    const float* ln1_b   = (const float*)d_in[10];
    const float* ln2_g   = (const float*)d_in[11];
    const float* ln2_b   = (const float*)d_in[12];
    const float* W1      = (const float*)d_in[13];
    const float* b1      = (const float*)d_in[14];
    const float* W2      = (const float*)d_in[15];
    const float* b2      = (const float*)d_in[16];
    const float* Wlm     = (const float*)d_in[17];
    const float* blm     = (const float*)d_in[18];

    float *x, *h, *q, *k, *v, *o, *ff, *att, *nll;
    cudaGetSymbolAddress((void**)&x,   g_x);
    cudaGetSymbolAddress((void**)&h,   g_h);
    cudaGetSymbolAddress((void**)&q,   g_q);
    cudaGetSymbolAddress((void**)&k,   g_k);
    cudaGetSymbolAddress((void**)&v,   g_v);
    cudaGetSymbolAddress((void**)&o,   g_o);
    cudaGetSymbolAddress((void**)&ff,  g_ff);
    cudaGetSymbolAddress((void**)&att, g_att);
    cudaGetSymbolAddress((void**)&nll, g_nll);

    cudaFuncSetAttribute(gemm_tf32, cudaFuncAttributeMaxDynamicSharedMemorySize, GSMEM);

    embed_kernel<<<(BT * D + 255) / 256, 256>>>(idx, tok_emb, pos_emb, x);

    dim3 gD(BT / 128, D / 64);               // 32 x 12
    dim3 gF(BT / 128, FF / 64);              // 32 x 48
    dim3 gV(BT / 128, (VV + 63) / 64);       // 32 x 786

    for (int l = 0; l < NL; l++) {
        const float* wq = Wq + (size_t)l * D * D;
        const float* wk = Wk + (size_t)l * D * D;
        const float* wv = Wv + (size_t)l * D * D;
        const float* wo = Wo + (size_t)l * D * D;
        const float* w1 = W1 + (size_t)l * D * FF;
        const float* w2 = W2 + (size_t)l * FF * D;

        ln_kernel<<<BT, 256>>>(x, ln1_g + (size_t)l * D, ln1_b + (size_t)l * D, h);
        gemm_tf32<<<gD, 128, GSMEM>>>(h, wq, nullptr, nullptr, q, BT, D, D, 0, 0);
        gemm_tf32<<<gD, 128, GSMEM>>>(h, wk, nullptr, nullptr, k, BT, D, D, 0, 0);
        gemm_tf32<<<gD, 128, GSMEM>>>(h, wv, nullptr, nullptr, v, BT, D, D, 0, 0);

        attn_scores<<<dim3(TT / 64, TT / 64, BH), 128>>>(q, k, att);
        attn_softmax<<<BH * TT, 256>>>(att);
        attn_pv<<<dim3(TT / 64, BH), 128>>>(att, v, o);

        gemm_tf32<<<gD, 128, GSMEM>>>(o, wo, bo + (size_t)l * D, x, x, BT, D, D, 0, 0);

        ln_kernel<<<BT, 256>>>(x, ln2_g + (size_t)l * D, ln2_b + (size_t)l * D, h);
        gemm_tf32<<<gF, 128, GSMEM>>>(h, w1, b1 + (size_t)l * FF, nullptr, ff, BT, FF, D, 1, 1);
        gemm_tf32<<<gD, 128, GSMEM>>>(ff, w2, b2 + (size_t)l * D, x, x, BT, D, FF, 0, 0);
    }

    // rounded copy of x for the LM head A operand
    round_kernel<<<1024, 256>>>(x, h, (long long)BT * D);

    float* logits = (float*)d_out;
    gemm_tf32<<<gV, 128, GSMEM>>>(h, Wlm, blm, nullptr, logits, BT, VV, D, 0, 0);

    long long btv = (long long)BT * VV;
    if ((long long)out_size > btv) {
        nll_kernel<<<BT, 256>>>(logits, targets, nll);
        loss_kernel<<<1, 256>>>(nll, logits + btv, (int)((long long)out_size - btv));
    }
}